// round 10
// baseline (speedup 1.0000x reference)
#include <cuda_runtime.h>
#include <cuda_fp16.h>
#include <stdint.h>
#include <math.h>

#define BATCH  4
#define CDIM   192
#define NHEADS 8
#define HDIM   24
#define HWN    65536
#define OC3    576
#define KDIM   192
#define NTILES 8
#define KPADH  200   // A row pad (halves)
#define NPADH  136   // B row pad (halves)

// ---- scratch (device globals) ----
__device__ __half g_qkvh[(size_t)BATCH * OC3 * HWN];  // 1x1-conv out, fp16
__device__ __half g_ch  [(size_t)BATCH * OC3 * HWN];  // dwconv out, fp16
__device__ float  g_g48 [BATCH * NHEADS * 48 * 48];   // [q;k] full gram
__device__ float  g_M   [BATCH * CDIM * CDIM];

__device__ __forceinline__ uint32_t smem_u32(const void* p) {
    uint32_t a;
    asm("{ .reg .u64 t; cvta.to.shared.u64 t, %1; cvt.u32.u64 %0, t; }" : "=r"(a) : "l"(p));
    return a;
}
__device__ __forceinline__ uint32_t h2u(__half2 h) { return *(uint32_t*)&h; }

#define LDSM_X4(r, addr) \
    asm volatile("ldmatrix.sync.aligned.m8n8.x4.shared.b16 {%0,%1,%2,%3}, [%4];" \
        : "=r"((r)[0]), "=r"((r)[1]), "=r"((r)[2]), "=r"((r)[3]) : "r"(addr))
#define LDSM_X4_T(r, addr) \
    asm volatile("ldmatrix.sync.aligned.m8n8.x4.trans.shared.b16 {%0,%1,%2,%3}, [%4];" \
        : "=r"((r)[0]), "=r"((r)[1]), "=r"((r)[2]), "=r"((r)[3]) : "r"(addr))
#define MMA_F16(cc, aa, b0, b1) \
    asm volatile("mma.sync.aligned.m16n8k16.row.col.f32.f16.f16.f32 " \
        "{%0,%1,%2,%3}, {%4,%5,%6,%7}, {%8,%9}, {%0,%1,%2,%3};" \
        : "+f"((cc)[0]), "+f"((cc)[1]), "+f"((cc)[2]), "+f"((cc)[3]) \
        : "r"((aa)[0]), "r"((aa)[1]), "r"((aa)[2]), "r"((aa)[3]), "r"(b0), "r"(b1))

// ============================================================
// fp16 HMMA GEMM: C[b][m][n] = sum_k A[b][m][k] * B[b][k][n]
// ============================================================
template<bool BH, bool OH>
__global__ __launch_bounds__(256) void gemm_f16(
    const float* __restrict__ A, size_t aStride, int Mreal,
    const void* __restrict__ Bv, size_t bStride,
    void* __restrict__ C, size_t cStride)
{
    extern __shared__ __half hsm[];
    __half* As  = hsm;                       // [128][KPADH]
    __half* Bs0 = As + 128 * KPADH;          // [64][NPADH]
    __half* Bs1 = Bs0 + 64 * NPADH;

    const float*  Bf = (const float*)Bv;
    const __half* Bh = (const __half*)Bv;
    float*  Cf = (float*)C;
    __half* Ch = (__half*)C;

    int tid  = threadIdx.x;
    int warp = tid >> 5, lane = tid & 31;
    int g = lane >> 2, t = lane & 3;
    int wm0 = (warp >> 1) * 32;
    int wn0 = (warp & 1) * 64;

    int m0    = blockIdx.x * 128;
    int b     = blockIdx.z;
    int nBase = blockIdx.y * (128 * NTILES);
    const float* Ab = A + (size_t)b * aStride;
    size_t bOff = (size_t)b * bStride;
    size_t cOff = (size_t)b * cStride;

    for (int it = tid; it < 128 * 48; it += 256) {
        int row = it / 48, c4 = (it - row * 48) * 4;
        float4 v = make_float4(0.f, 0.f, 0.f, 0.f);
        if (m0 + row < Mreal) v = *(const float4*)&Ab[(size_t)(m0 + row) * KDIM + c4];
        uint2 u;
        u.x = h2u(__float22half2_rn(make_float2(v.x, v.y)));
        u.y = h2u(__float22half2_rn(make_float2(v.z, v.w)));
        *(uint2*)(As + row * KPADH + c4) = u;
    }

    int kr  = tid >> 5;
    int lc4 = lane * 4;
    float4 pf[8];
    uint2  pf2[8];

    float c[2][8][4];
#pragma unroll
    for (int mt = 0; mt < 2; mt++)
#pragma unroll
        for (int nt = 0; nt < 8; nt++)
#pragma unroll
            for (int j = 0; j < 4; j++) c[mt][nt][j] = 0.f;

    const int TOT = NTILES * 3;
    uint32_t sA  = smem_u32(As);
    uint32_t sB0 = smem_u32(Bs0);
    uint32_t sB1 = smem_u32(Bs1);

    {
        if (BH) {
#pragma unroll
            for (int j = 0; j < 8; j++)
                pf2[j] = *(const uint2*)&Bh[bOff + (size_t)(kr + 8 * j) * HWN + nBase + lc4];
        } else {
#pragma unroll
            for (int j = 0; j < 8; j++)
                pf[j] = *(const float4*)&Bf[bOff + (size_t)(kr + 8 * j) * HWN + nBase + lc4];
        }
#pragma unroll
        for (int j = 0; j < 8; j++) {
            uint2 u;
            if (BH) u = pf2[j];
            else {
                u.x = h2u(__float22half2_rn(make_float2(pf[j].x, pf[j].y)));
                u.y = h2u(__float22half2_rn(make_float2(pf[j].z, pf[j].w)));
            }
            *(uint2*)(Bs0 + (kr + 8 * j) * NPADH + lc4) = u;
        }
    }
    __syncthreads();

    for (int i = 0; i < TOT; i++) {
        int tile = i / 3;
        int kc   = i - tile * 3;

        if (i + 1 < TOT) {
            int ntile = (i + 1) / 3;
            int nkc   = (i + 1) - ntile * 3;
            size_t src = bOff + (size_t)(nkc * 64 + kr) * HWN + nBase + ntile * 128 + lc4;
            if (BH) {
#pragma unroll
                for (int j = 0; j < 8; j++) pf2[j] = *(const uint2*)&Bh[src + (size_t)j * 8 * HWN];
            } else {
#pragma unroll
                for (int j = 0; j < 8; j++) pf[j] = *(const float4*)&Bf[src + (size_t)j * 8 * HWN];
            }
        }

        uint32_t sB = (i & 1) ? sB1 : sB0;
#pragma unroll
        for (int ks = 0; ks < 4; ks++) {
            uint32_t a[2][4];
            int kA = kc * 64 + ks * 16 + ((lane >> 4) << 3);
#pragma unroll
            for (int mt = 0; mt < 2; mt++) {
                int row = wm0 + mt * 16 + (lane & 15);
                LDSM_X4(a[mt], sA + (uint32_t)(row * KPADH + kA) * 2);
            }
#pragma unroll
            for (int pr = 0; pr < 4; pr++) {
                uint32_t bq[4];
                int brow = ks * 16 + (lane & 15);
                int bcol = wn0 + pr * 16 + ((lane >> 4) << 3);
                LDSM_X4_T(bq, sB + (uint32_t)(brow * NPADH + bcol) * 2);
                MMA_F16(c[0][2 * pr],     a[0], bq[0], bq[1]);
                MMA_F16(c[1][2 * pr],     a[1], bq[0], bq[1]);
                MMA_F16(c[0][2 * pr + 1], a[0], bq[2], bq[3]);
                MMA_F16(c[1][2 * pr + 1], a[1], bq[2], bq[3]);
            }
        }

        if (kc == 2) {
            int n0 = nBase + tile * 128;
#pragma unroll
            for (int mt = 0; mt < 2; mt++) {
                int row0 = m0 + wm0 + mt * 16 + g;
#pragma unroll
                for (int nt = 0; nt < 8; nt++) {
                    int col = n0 + wn0 + nt * 8 + 2 * t;
                    if (row0 < Mreal) {
                        if (OH) *(__half2*)&Ch[cOff + (size_t)row0 * HWN + col] =
                            __floats2half2_rn(c[mt][nt][0], c[mt][nt][1]);
                        else {
                            float2 v = {c[mt][nt][0], c[mt][nt][1]};
                            *(float2*)&Cf[cOff + (size_t)row0 * HWN + col] = v;
                        }
                    }
                    if (row0 + 8 < Mreal) {
                        if (OH) *(__half2*)&Ch[cOff + (size_t)(row0 + 8) * HWN + col] =
                            __floats2half2_rn(c[mt][nt][2], c[mt][nt][3]);
                        else {
                            float2 v = {c[mt][nt][2], c[mt][nt][3]};
                            *(float2*)&Cf[cOff + (size_t)(row0 + 8) * HWN + col] = v;
                        }
                    }
                    c[mt][nt][0] = 0.f; c[mt][nt][1] = 0.f;
                    c[mt][nt][2] = 0.f; c[mt][nt][3] = 0.f;
                }
            }
        }

        if (i + 1 < TOT) {
            __half* nbuf = (i & 1) ? Bs0 : Bs1;
#pragma unroll
            for (int j = 0; j < 8; j++) {
                uint2 u;
                if (BH) u = pf2[j];
                else {
                    u.x = h2u(__float22half2_rn(make_float2(pf[j].x, pf[j].y)));
                    u.y = h2u(__float22half2_rn(make_float2(pf[j].z, pf[j].w)));
                }
                *(uint2*)(nbuf + (kr + 8 * j) * NPADH + lc4) = u;
            }
            __syncthreads();
        }
    }
}

// ============================================================
// depthwise 3x3, fp16 in -> fp16 out, 8 px per thread (deep MLP)
// ============================================================
__global__ __launch_bounds__(256) void dwconv_all(
    const __half* __restrict__ in, const float* __restrict__ wAll,
    __half* __restrict__ out)
{
    int idx = blockIdx.x * 256 + threadIdx.x;
    int p8 = idx & 8191;
    int bc = idx >> 13;
    int ch = bc % OC3;
    int y  = p8 >> 5;
    int x0 = (p8 & 31) << 3;
    const __half* base = in + (size_t)bc * HWN;

    float w[9];
#pragma unroll
    for (int i = 0; i < 9; i++) w[i] = __ldg(&wAll[ch * 9 + i]);

    uint4 rowv[3];
    float lft[3], rgt[3];
    bool ok[3];
#pragma unroll
    for (int ky = 0; ky < 3; ky++) {
        int yy = y + ky - 1;
        ok[ky] = ((unsigned)yy < 256u);
        const __half* row = base + yy * 256;
        if (ok[ky]) {
            rowv[ky] = *(const uint4*)&row[x0];
            lft[ky]  = (x0 > 0)   ? __half2float(row[x0 - 1]) : 0.f;
            rgt[ky]  = (x0 < 248) ? __half2float(row[x0 + 8]) : 0.f;
        }
    }

    float s[8];
#pragma unroll
    for (int o = 0; o < 8; o++) s[o] = 0.f;

#pragma unroll
    for (int ky = 0; ky < 3; ky++) {
        if (!ok[ky]) continue;
        float f[10];
        const __half* hp = (const __half*)&rowv[ky];
        f[0] = lft[ky];
#pragma unroll
        for (int j = 0; j < 8; j++) f[j + 1] = __half2float(hp[j]);
        f[9] = rgt[ky];
        float w0 = w[ky * 3], w1 = w[ky * 3 + 1], w2 = w[ky * 3 + 2];
#pragma unroll
        for (int o = 0; o < 8; o++)
            s[o] += f[o] * w0 + f[o + 1] * w1 + f[o + 2] * w2;
    }

    uint4 u;
    u.x = h2u(__floats2half2_rn(s[0], s[1]));
    u.y = h2u(__floats2half2_rn(s[2], s[3]));
    u.z = h2u(__floats2half2_rn(s[4], s[5]));
    u.w = h2u(__floats2half2_rn(s[6], s[7]));
    *(uint4*)&out[(size_t)idx * 8] = u;
}

__global__ void zero_g48() {
    int i = blockIdx.x * blockDim.x + threadIdx.x;
    if (i < BATCH * NHEADS * 48 * 48) g_g48[i] = 0.f;
}

// ============================================================
// Tensor-core gram v3: double-buffered 256-px tiles, 1 barrier/iter.
// 192 threads = 6 warps = 2 pixel-halves (128 px) x 3 m-tiles.
// ============================================================
#define GTPAD 264     // 528 B rows: 8-row ldmatrix spans all 32 banks
__global__ __launch_bounds__(192) void gram_tc(const __half* __restrict__ chd, int pxPer)
{
    extern __shared__ __half gsm[];          // [2][48][GTPAD]
    __half* buf0 = gsm;
    __half* buf1 = gsm + 48 * GTPAD;

    int bh = blockIdx.y;
    int b = bh >> 3, hh = bh & 7;
    int tid = threadIdx.x;
    int warp = tid >> 5, lane = tid & 31;
    int half = warp / 3;
    int mt   = warp - half * 3;
    int m0 = mt * 16;
    int colBase = half * 128;

    int lrow = tid >> 2;                 // 0..47
    int lseg0 = (tid & 3) * 8;           // 8 consecutive uint4 segs
    int lgch = (lrow < 24) ? (hh * HDIM + lrow) : (CDIM + hh * HDIM + (lrow - 24));
    const __half* lsrc = chd + ((size_t)b * OC3 + lgch) * HWN;

    float c[6][4];
#pragma unroll
    for (int nt = 0; nt < 6; nt++)
#pragma unroll
        for (int j = 0; j < 4; j++) c[nt][j] = 0.f;

    int aRow = m0 + (lane & 15);
    int aK   = colBase + ((lane >> 4) << 3);
    int bRowLoc = ((lane >> 4) << 3) + (lane & 7);
    int bK      = colBase + (((lane >> 3) & 1) << 3);
    uint32_t sb0 = smem_u32(buf0);
    uint32_t sb1 = smem_u32(buf1);

    int nStart = blockIdx.x * pxPer;
    int nIters = pxPer / 256;

    {   // prologue: tile 0
#pragma unroll
        for (int j = 0; j < 8; j++)
            *(uint4*)&buf0[lrow * GTPAD + (lseg0 + j) * 8] =
                *(const uint4*)&lsrc[nStart + (lseg0 + j) * 8];
    }
    __syncthreads();

    for (int it = 0; it < nIters; it++) {
        if (it + 1 < nIters) {
            const __half* src = lsrc + nStart + (it + 1) * 256;
            __half* d = ((it + 1) & 1) ? buf1 : buf0;
#pragma unroll
            for (int j = 0; j < 8; j++)
                *(uint4*)&d[lrow * GTPAD + (lseg0 + j) * 8] =
                    *(const uint4*)&src[(lseg0 + j) * 8];
        }

        uint32_t sB = (it & 1) ? sb1 : sb0;
        uint32_t aAddr = sB + (uint32_t)(aRow * GTPAD + aK) * 2;
#pragma unroll
        for (int ks = 0; ks < 8; ks++) {
            uint32_t a[4];
            LDSM_X4(a, aAddr + (uint32_t)(ks * 16) * 2);
#pragma unroll
            for (int nb = 0; nb < 3; nb++) {
                uint32_t bq[4];
                int nr = nb * 16 + bRowLoc;
                LDSM_X4(bq, sB + (uint32_t)(nr * GTPAD + bK + ks * 16) * 2);
                MMA_F16(c[2 * nb],     a, bq[0], bq[1]);
                MMA_F16(c[2 * nb + 1], a, bq[2], bq[3]);
            }
        }
        __syncthreads();
    }

    float* gb = &g_g48[bh * 2304];
    int gm = lane >> 2, gt2 = (lane & 3) * 2;
#pragma unroll
    for (int nt = 0; nt < 6; nt++) {
        int col = nt * 8 + gt2;
        atomicAdd(&gb[(m0 + gm) * 48 + col],     c[nt][0]);
        atomicAdd(&gb[(m0 + gm) * 48 + col + 1], c[nt][1]);
        atomicAdd(&gb[(m0 + gm + 8) * 48 + col],     c[nt][2]);
        atomicAdd(&gb[(m0 + gm + 8) * 48 + col + 1], c[nt][3]);
    }
}

// ============================================================
// softmax + fold proj -> per-batch M (fp32)
// ============================================================
__global__ __launch_bounds__(256) void attn_proj_kernel(
    const float* __restrict__ projw, const float* __restrict__ temp)
{
    __shared__ float attn_s[NHEADS * HDIM * HDIM];
    int b = blockIdx.x;
    int t = threadIdx.x;
    if (t < CDIM) {
        int hh = t / HDIM, d = t % HDIM;
        const float* G = &g_g48[(b * NHEADS + hh) * 2304];
        float nq = fmaxf(sqrtf(G[d * 48 + d]), 1e-12f);
        float tm = temp[hh];
        float row[HDIM];
        float mx = -1e30f;
#pragma unroll
        for (int e = 0; e < HDIM; e++) {
            float nk = fmaxf(sqrtf(G[(24 + e) * 48 + 24 + e]), 1e-12f);
            float a = G[d * 48 + 24 + e] / (nq * nk) * tm;
            row[e] = a; mx = fmaxf(mx, a);
        }
        float s = 0.f;
#pragma unroll
        for (int e = 0; e < HDIM; e++) { row[e] = expf(row[e] - mx); s += row[e]; }
        float inv = 1.f / s;
#pragma unroll
        for (int e = 0; e < HDIM; e++) attn_s[hh * 576 + d * 24 + e] = row[e] * inv;
    }
    __syncthreads();
    if (t < CDIM) {
        int o = t;
        const float* pr = &projw[o * CDIM];
        for (int hh = 0; hh < NHEADS; hh++) {
#pragma unroll
            for (int e = 0; e < HDIM; e++) {
                float acc = 0.f;
#pragma unroll
                for (int d = 0; d < HDIM; d++)
                    acc += pr[hh * 24 + d] * attn_s[hh * 576 + d * 24 + e];
                g_M[((size_t)b * CDIM + o) * CDIM + hh * 24 + e] = acc;
            }
        }
    }
}

// ============================================================
extern "C" void kernel_launch(void* const* d_in, const int* in_sizes, int n_in,
                              void* d_out, int out_size)
{
    const float* x      = (const float*)d_in[0];
    const float* qkv_w  = (const float*)d_in[1];
    const float* dw_w   = (const float*)d_in[2];
    const float* proj_w = (const float*)d_in[3];
    const float* temp   = (const float*)d_in[4];
    float* out = (float*)d_out;

    __half *qkvh, *chd;
    float *Mp;
    cudaGetSymbolAddress((void**)&qkvh, g_qkvh);
    cudaGetSymbolAddress((void**)&chd,  g_ch);
    cudaGetSymbolAddress((void**)&Mp,   g_M);

    const int GEMM_SMEM = (128 * KPADH + 2 * 64 * NPADH) * 2;
    const int GRAM_SMEM = 2 * 48 * GTPAD * 2;
    cudaFuncSetAttribute(gemm_f16<false, true>, cudaFuncAttributeMaxDynamicSharedMemorySize, GEMM_SMEM);
    cudaFuncSetAttribute(gemm_f16<true, false>, cudaFuncAttributeMaxDynamicSharedMemorySize, GEMM_SMEM);
    cudaFuncSetAttribute(gram_tc, cudaFuncAttributeMaxDynamicSharedMemorySize, GRAM_SMEM);

    zero_g48<<<(BATCH * NHEADS * 2304 + 255) / 256, 256>>>();

    // K1: qkv = W_qkv @ x  (fp16 MMA, fp32 B in, fp16 C out)
    dim3 g1(5, HWN / (128 * NTILES), BATCH);
    gemm_f16<false, true><<<g1, 256, GEMM_SMEM>>>(qkv_w, 0, OC3,
                                                  x, (size_t)CDIM * HWN,
                                                  qkvh, (size_t)OC3 * HWN);

    // K2: depthwise 3x3, all channels, fp16->fp16, 8 px/thread
    dwconv_all<<<(BATCH * OC3 * HWN / 8) / 256, 256>>>(qkvh, dw_w, chd);

    // K3: tensor-core gram, double-buffered 256-px tiles
    dim3 g3(32, BATCH * NHEADS);
    gram_tc<<<g3, 192, GRAM_SMEM>>>(chd, HWN / 32);

    // K4: softmax + fold proj
    attn_proj_kernel<<<BATCH, 256>>>(proj_w, temp);

    // K5: out = M_b @ v  (fp16 MMA, fp16 B in, fp32 C out)
    dim3 g5(2, HWN / (128 * NTILES), BATCH);
    gemm_f16<true, false><<<g5, 256, GEMM_SMEM>>>(Mp, (size_t)CDIM * CDIM, CDIM,
                                                  chd + (size_t)2 * CDIM * HWN, (size_t)OC3 * HWN,
                                                  out, (size_t)CDIM * HWN);
}

// round 11
// speedup vs baseline: 1.0669x; 1.0669x over previous
#include <cuda_runtime.h>
#include <cuda_fp16.h>
#include <stdint.h>
#include <math.h>

#define BATCH  4
#define CDIM   192
#define NHEADS 8
#define HDIM   24
#define HWN    65536
#define OC3    576
#define KDIM   192
#define NTILES 8
#define KPADH  200   // A row pad (halves)
#define NPADH  136   // B row pad (halves)

// ---- scratch (device globals) ----
__device__ __half g_qkvh[(size_t)BATCH * OC3 * HWN];  // 1x1-conv out, fp16
__device__ __half g_ch  [(size_t)BATCH * OC3 * HWN];  // dwconv out, fp16
__device__ float  g_g48 [BATCH * NHEADS * 48 * 48];   // [q;k] full gram
__device__ float  g_M   [BATCH * CDIM * CDIM];

__device__ __forceinline__ uint32_t smem_u32(const void* p) {
    uint32_t a;
    asm("{ .reg .u64 t; cvta.to.shared.u64 t, %1; cvt.u32.u64 %0, t; }" : "=r"(a) : "l"(p));
    return a;
}
__device__ __forceinline__ uint32_t h2u(__half2 h) { return *(uint32_t*)&h; }

#define LDSM_X4(r, addr) \
    asm volatile("ldmatrix.sync.aligned.m8n8.x4.shared.b16 {%0,%1,%2,%3}, [%4];" \
        : "=r"((r)[0]), "=r"((r)[1]), "=r"((r)[2]), "=r"((r)[3]) : "r"(addr))
#define LDSM_X4_T(r, addr) \
    asm volatile("ldmatrix.sync.aligned.m8n8.x4.trans.shared.b16 {%0,%1,%2,%3}, [%4];" \
        : "=r"((r)[0]), "=r"((r)[1]), "=r"((r)[2]), "=r"((r)[3]) : "r"(addr))
#define MMA_F16(cc, aa, b0, b1) \
    asm volatile("mma.sync.aligned.m16n8k16.row.col.f32.f16.f16.f32 " \
        "{%0,%1,%2,%3}, {%4,%5,%6,%7}, {%8,%9}, {%0,%1,%2,%3};" \
        : "+f"((cc)[0]), "+f"((cc)[1]), "+f"((cc)[2]), "+f"((cc)[3]) \
        : "r"((aa)[0]), "r"((aa)[1]), "r"((aa)[2]), "r"((aa)[3]), "r"(b0), "r"(b1))
#define CP_ASYNC16(dst, src) \
    asm volatile("cp.async.cg.shared.global [%0], [%1], 16;" :: "r"(dst), "l"(src) : "memory")
#define CP_COMMIT() asm volatile("cp.async.commit_group;" ::: "memory")
#define CP_WAIT(n)  asm volatile("cp.async.wait_group %0;" :: "n"(n) : "memory")

// ============================================================
// fp16 HMMA GEMM: C[b][m][n] = sum_k A[b][m][k] * B[b][k][n]
// (unchanged from the validated 699us version)
// ============================================================
template<bool BH, bool OH>
__global__ __launch_bounds__(256) void gemm_f16(
    const float* __restrict__ A, size_t aStride, int Mreal,
    const void* __restrict__ Bv, size_t bStride,
    void* __restrict__ C, size_t cStride)
{
    extern __shared__ __half hsm[];
    __half* As  = hsm;                       // [128][KPADH]
    __half* Bs0 = As + 128 * KPADH;          // [64][NPADH]
    __half* Bs1 = Bs0 + 64 * NPADH;

    const float*  Bf = (const float*)Bv;
    const __half* Bh = (const __half*)Bv;
    float*  Cf = (float*)C;
    __half* Ch = (__half*)C;

    int tid  = threadIdx.x;
    int warp = tid >> 5, lane = tid & 31;
    int g = lane >> 2, t = lane & 3;
    int wm0 = (warp >> 1) * 32;
    int wn0 = (warp & 1) * 64;

    int m0    = blockIdx.x * 128;
    int b     = blockIdx.z;
    int nBase = blockIdx.y * (128 * NTILES);
    const float* Ab = A + (size_t)b * aStride;
    size_t bOff = (size_t)b * bStride;
    size_t cOff = (size_t)b * cStride;

    for (int it = tid; it < 128 * 48; it += 256) {
        int row = it / 48, c4 = (it - row * 48) * 4;
        float4 v = make_float4(0.f, 0.f, 0.f, 0.f);
        if (m0 + row < Mreal) v = *(const float4*)&Ab[(size_t)(m0 + row) * KDIM + c4];
        uint2 u;
        u.x = h2u(__float22half2_rn(make_float2(v.x, v.y)));
        u.y = h2u(__float22half2_rn(make_float2(v.z, v.w)));
        *(uint2*)(As + row * KPADH + c4) = u;
    }

    int kr  = tid >> 5;
    int lc4 = lane * 4;
    float4 pf[8];
    uint2  pf2[8];

    float c[2][8][4];
#pragma unroll
    for (int mt = 0; mt < 2; mt++)
#pragma unroll
        for (int nt = 0; nt < 8; nt++)
#pragma unroll
            for (int j = 0; j < 4; j++) c[mt][nt][j] = 0.f;

    const int TOT = NTILES * 3;
    uint32_t sA  = smem_u32(As);
    uint32_t sB0 = smem_u32(Bs0);
    uint32_t sB1 = smem_u32(Bs1);

    {
        if (BH) {
#pragma unroll
            for (int j = 0; j < 8; j++)
                pf2[j] = *(const uint2*)&Bh[bOff + (size_t)(kr + 8 * j) * HWN + nBase + lc4];
        } else {
#pragma unroll
            for (int j = 0; j < 8; j++)
                pf[j] = *(const float4*)&Bf[bOff + (size_t)(kr + 8 * j) * HWN + nBase + lc4];
        }
#pragma unroll
        for (int j = 0; j < 8; j++) {
            uint2 u;
            if (BH) u = pf2[j];
            else {
                u.x = h2u(__float22half2_rn(make_float2(pf[j].x, pf[j].y)));
                u.y = h2u(__float22half2_rn(make_float2(pf[j].z, pf[j].w)));
            }
            *(uint2*)(Bs0 + (kr + 8 * j) * NPADH + lc4) = u;
        }
    }
    __syncthreads();

    for (int i = 0; i < TOT; i++) {
        int tile = i / 3;
        int kc   = i - tile * 3;

        if (i + 1 < TOT) {
            int ntile = (i + 1) / 3;
            int nkc   = (i + 1) - ntile * 3;
            size_t src = bOff + (size_t)(nkc * 64 + kr) * HWN + nBase + ntile * 128 + lc4;
            if (BH) {
#pragma unroll
                for (int j = 0; j < 8; j++) pf2[j] = *(const uint2*)&Bh[src + (size_t)j * 8 * HWN];
            } else {
#pragma unroll
                for (int j = 0; j < 8; j++) pf[j] = *(const float4*)&Bf[src + (size_t)j * 8 * HWN];
            }
        }

        uint32_t sB = (i & 1) ? sB1 : sB0;
#pragma unroll
        for (int ks = 0; ks < 4; ks++) {
            uint32_t a[2][4];
            int kA = kc * 64 + ks * 16 + ((lane >> 4) << 3);
#pragma unroll
            for (int mt = 0; mt < 2; mt++) {
                int row = wm0 + mt * 16 + (lane & 15);
                LDSM_X4(a[mt], sA + (uint32_t)(row * KPADH + kA) * 2);
            }
#pragma unroll
            for (int pr = 0; pr < 4; pr++) {
                uint32_t bq[4];
                int brow = ks * 16 + (lane & 15);
                int bcol = wn0 + pr * 16 + ((lane >> 4) << 3);
                LDSM_X4_T(bq, sB + (uint32_t)(brow * NPADH + bcol) * 2);
                MMA_F16(c[0][2 * pr],     a[0], bq[0], bq[1]);
                MMA_F16(c[1][2 * pr],     a[1], bq[0], bq[1]);
                MMA_F16(c[0][2 * pr + 1], a[0], bq[2], bq[3]);
                MMA_F16(c[1][2 * pr + 1], a[1], bq[2], bq[3]);
            }
        }

        if (kc == 2) {
            int n0 = nBase + tile * 128;
#pragma unroll
            for (int mt = 0; mt < 2; mt++) {
                int row0 = m0 + wm0 + mt * 16 + g;
#pragma unroll
                for (int nt = 0; nt < 8; nt++) {
                    int col = n0 + wn0 + nt * 8 + 2 * t;
                    if (row0 < Mreal) {
                        if (OH) *(__half2*)&Ch[cOff + (size_t)row0 * HWN + col] =
                            __floats2half2_rn(c[mt][nt][0], c[mt][nt][1]);
                        else {
                            float2 v = {c[mt][nt][0], c[mt][nt][1]};
                            *(float2*)&Cf[cOff + (size_t)row0 * HWN + col] = v;
                        }
                    }
                    if (row0 + 8 < Mreal) {
                        if (OH) *(__half2*)&Ch[cOff + (size_t)(row0 + 8) * HWN + col] =
                            __floats2half2_rn(c[mt][nt][2], c[mt][nt][3]);
                        else {
                            float2 v = {c[mt][nt][2], c[mt][nt][3]};
                            *(float2*)&Cf[cOff + (size_t)(row0 + 8) * HWN + col] = v;
                        }
                    }
                    c[mt][nt][0] = 0.f; c[mt][nt][1] = 0.f;
                    c[mt][nt][2] = 0.f; c[mt][nt][3] = 0.f;
                }
            }
        }

        if (i + 1 < TOT) {
            __half* nbuf = (i & 1) ? Bs0 : Bs1;
#pragma unroll
            for (int j = 0; j < 8; j++) {
                uint2 u;
                if (BH) u = pf2[j];
                else {
                    u.x = h2u(__float22half2_rn(make_float2(pf[j].x, pf[j].y)));
                    u.y = h2u(__float22half2_rn(make_float2(pf[j].z, pf[j].w)));
                }
                *(uint2*)(nbuf + (kr + 8 * j) * NPADH + lc4) = u;
            }
            __syncthreads();
        }
    }
}

// ============================================================
// depthwise 3x3, fp16 in -> fp16 out, 8 px per thread
// ============================================================
__global__ __launch_bounds__(256) void dwconv_all(
    const __half* __restrict__ in, const float* __restrict__ wAll,
    __half* __restrict__ out)
{
    int idx = blockIdx.x * 256 + threadIdx.x;
    int p8 = idx & 8191;
    int bc = idx >> 13;
    int ch = bc % OC3;
    int y  = p8 >> 5;
    int x0 = (p8 & 31) << 3;
    const __half* base = in + (size_t)bc * HWN;

    float w[9];
#pragma unroll
    for (int i = 0; i < 9; i++) w[i] = __ldg(&wAll[ch * 9 + i]);

    uint4 rowv[3];
    float lft[3], rgt[3];
    bool ok[3];
#pragma unroll
    for (int ky = 0; ky < 3; ky++) {
        int yy = y + ky - 1;
        ok[ky] = ((unsigned)yy < 256u);
        const __half* row = base + yy * 256;
        if (ok[ky]) {
            rowv[ky] = *(const uint4*)&row[x0];
            lft[ky]  = (x0 > 0)   ? __half2float(row[x0 - 1]) : 0.f;
            rgt[ky]  = (x0 < 248) ? __half2float(row[x0 + 8]) : 0.f;
        }
    }

    float s[8];
#pragma unroll
    for (int o = 0; o < 8; o++) s[o] = 0.f;

#pragma unroll
    for (int ky = 0; ky < 3; ky++) {
        if (!ok[ky]) continue;
        float f[10];
        const __half* hp = (const __half*)&rowv[ky];
        f[0] = lft[ky];
#pragma unroll
        for (int j = 0; j < 8; j++) f[j + 1] = __half2float(hp[j]);
        f[9] = rgt[ky];
        float w0 = w[ky * 3], w1 = w[ky * 3 + 1], w2 = w[ky * 3 + 2];
#pragma unroll
        for (int o = 0; o < 8; o++)
            s[o] += f[o] * w0 + f[o + 1] * w1 + f[o + 2] * w2;
    }

    uint4 u;
    u.x = h2u(__floats2half2_rn(s[0], s[1]));
    u.y = h2u(__floats2half2_rn(s[2], s[3]));
    u.z = h2u(__floats2half2_rn(s[4], s[5]));
    u.w = h2u(__floats2half2_rn(s[6], s[7]));
    *(uint4*)&out[(size_t)idx * 8] = u;
}

__global__ void zero_g48() {
    int i = blockIdx.x * blockDim.x + threadIdx.x;
    if (i < BATCH * NHEADS * 48 * 48) g_g48[i] = 0.f;
}

// ============================================================
// Tensor-core gram v4: cp.async double-buffered 256-px tiles.
// 192 threads = 6 warps = 2 pixel-halves (128 px) x 3 m-tiles.
// ============================================================
#define GTPAD 264     // 528 B rows: 8-row ldmatrix spans all 32 banks
__global__ __launch_bounds__(192) void gram_tc(const __half* __restrict__ chd, int pxPer)
{
    extern __shared__ __half gsm[];          // [2][48][GTPAD]
    __half* buf0 = gsm;
    __half* buf1 = gsm + 48 * GTPAD;

    int bh = blockIdx.y;
    int b = bh >> 3, hh = bh & 7;
    int tid = threadIdx.x;
    int warp = tid >> 5, lane = tid & 31;
    int half = warp / 3;
    int mt   = warp - half * 3;
    int m0 = mt * 16;
    int colBase = half * 128;

    int lrow = tid >> 2;                 // 0..47
    int lseg0 = (tid & 3) * 8;           // 8 consecutive uint4 segs
    int lgch = (lrow < 24) ? (hh * HDIM + lrow) : (CDIM + hh * HDIM + (lrow - 24));
    const __half* lsrc = chd + ((size_t)b * OC3 + lgch) * HWN;

    float c[6][4];
#pragma unroll
    for (int nt = 0; nt < 6; nt++)
#pragma unroll
        for (int j = 0; j < 4; j++) c[nt][j] = 0.f;

    int aRow = m0 + (lane & 15);
    int aK   = colBase + ((lane >> 4) << 3);
    int bRowLoc = ((lane >> 4) << 3) + (lane & 7);
    int bK      = colBase + (((lane >> 3) & 1) << 3);
    uint32_t sb0 = smem_u32(buf0);
    uint32_t sb1 = smem_u32(buf1);
    uint32_t dRow0 = sb0 + (uint32_t)(lrow * GTPAD) * 2;
    uint32_t dRow1 = sb1 + (uint32_t)(lrow * GTPAD) * 2;

    int nStart = blockIdx.x * pxPer;
    int nIters = pxPer / 256;

    {   // prologue: tile 0 via cp.async
        const __half* src = lsrc + nStart;
#pragma unroll
        for (int j = 0; j < 8; j++)
            CP_ASYNC16(dRow0 + (uint32_t)((lseg0 + j) * 8) * 2, src + (lseg0 + j) * 8);
        CP_COMMIT();
    }

    for (int it = 0; it < nIters; it++) {
        if (it + 1 < nIters) {
            const __half* src = lsrc + nStart + (it + 1) * 256;
            uint32_t d = ((it + 1) & 1) ? dRow1 : dRow0;
#pragma unroll
            for (int j = 0; j < 8; j++)
                CP_ASYNC16(d + (uint32_t)((lseg0 + j) * 8) * 2, src + (lseg0 + j) * 8);
            CP_COMMIT();
            CP_WAIT(1);          // tile it complete; tile it+1 may be in flight
        } else {
            CP_WAIT(0);
        }
        __syncthreads();

        uint32_t sB = (it & 1) ? sb1 : sb0;
        uint32_t aAddr = sB + (uint32_t)(aRow * GTPAD + aK) * 2;
#pragma unroll
        for (int ks = 0; ks < 8; ks++) {
            uint32_t a[4];
            LDSM_X4(a, aAddr + (uint32_t)(ks * 16) * 2);
#pragma unroll
            for (int nb = 0; nb < 3; nb++) {
                uint32_t bq[4];
                int nr = nb * 16 + bRowLoc;
                LDSM_X4(bq, sB + (uint32_t)(nr * GTPAD + bK + ks * 16) * 2);
                MMA_F16(c[2 * nb],     a, bq[0], bq[1]);
                MMA_F16(c[2 * nb + 1], a, bq[2], bq[3]);
            }
        }
        __syncthreads();   // all reads of buf[it&1] done before iter it+1 overwrites it
    }

    float* gb = &g_g48[bh * 2304];
    int gm = lane >> 2, gt2 = (lane & 3) * 2;
#pragma unroll
    for (int nt = 0; nt < 6; nt++) {
        int col = nt * 8 + gt2;
        atomicAdd(&gb[(m0 + gm) * 48 + col],     c[nt][0]);
        atomicAdd(&gb[(m0 + gm) * 48 + col + 1], c[nt][1]);
        atomicAdd(&gb[(m0 + gm + 8) * 48 + col],     c[nt][2]);
        atomicAdd(&gb[(m0 + gm + 8) * 48 + col + 1], c[nt][3]);
    }
}

// ============================================================
// softmax + fold proj -> per-batch M (fp32)
// ============================================================
__global__ __launch_bounds__(256) void attn_proj_kernel(
    const float* __restrict__ projw, const float* __restrict__ temp)
{
    __shared__ float attn_s[NHEADS * HDIM * HDIM];
    int b = blockIdx.x;
    int t = threadIdx.x;
    if (t < CDIM) {
        int hh = t / HDIM, d = t % HDIM;
        const float* G = &g_g48[(b * NHEADS + hh) * 2304];
        float nq = fmaxf(sqrtf(G[d * 48 + d]), 1e-12f);
        float tm = temp[hh];
        float row[HDIM];
        float mx = -1e30f;
#pragma unroll
        for (int e = 0; e < HDIM; e++) {
            float nk = fmaxf(sqrtf(G[(24 + e) * 48 + 24 + e]), 1e-12f);
            float a = G[d * 48 + 24 + e] / (nq * nk) * tm;
            row[e] = a; mx = fmaxf(mx, a);
        }
        float s = 0.f;
#pragma unroll
        for (int e = 0; e < HDIM; e++) { row[e] = expf(row[e] - mx); s += row[e]; }
        float inv = 1.f / s;
#pragma unroll
        for (int e = 0; e < HDIM; e++) attn_s[hh * 576 + d * 24 + e] = row[e] * inv;
    }
    __syncthreads();
    if (t < CDIM) {
        int o = t;
        const float* pr = &projw[o * CDIM];
        for (int hh = 0; hh < NHEADS; hh++) {
#pragma unroll
            for (int e = 0; e < HDIM; e++) {
                float acc = 0.f;
#pragma unroll
                for (int d = 0; d < HDIM; d++)
                    acc += pr[hh * 24 + d] * attn_s[hh * 576 + d * 24 + e];
                g_M[((size_t)b * CDIM + o) * CDIM + hh * 24 + e] = acc;
            }
        }
    }
}

// ============================================================
extern "C" void kernel_launch(void* const* d_in, const int* in_sizes, int n_in,
                              void* d_out, int out_size)
{
    const float* x      = (const float*)d_in[0];
    const float* qkv_w  = (const float*)d_in[1];
    const float* dw_w   = (const float*)d_in[2];
    const float* proj_w = (const float*)d_in[3];
    const float* temp   = (const float*)d_in[4];
    float* out = (float*)d_out;

    __half *qkvh, *chd;
    float *Mp;
    cudaGetSymbolAddress((void**)&qkvh, g_qkvh);
    cudaGetSymbolAddress((void**)&chd,  g_ch);
    cudaGetSymbolAddress((void**)&Mp,   g_M);

    const int GEMM_SMEM = (128 * KPADH + 2 * 64 * NPADH) * 2;
    const int GRAM_SMEM = 2 * 48 * GTPAD * 2;
    cudaFuncSetAttribute(gemm_f16<false, true>, cudaFuncAttributeMaxDynamicSharedMemorySize, GEMM_SMEM);
    cudaFuncSetAttribute(gemm_f16<true, false>, cudaFuncAttributeMaxDynamicSharedMemorySize, GEMM_SMEM);
    cudaFuncSetAttribute(gram_tc, cudaFuncAttributeMaxDynamicSharedMemorySize, GRAM_SMEM);

    zero_g48<<<(BATCH * NHEADS * 2304 + 255) / 256, 256>>>();

    // K1: qkv = W_qkv @ x  (fp16 MMA, fp32 B in, fp16 C out)
    dim3 g1(5, HWN / (128 * NTILES), BATCH);
    gemm_f16<false, true><<<g1, 256, GEMM_SMEM>>>(qkv_w, 0, OC3,
                                                  x, (size_t)CDIM * HWN,
                                                  qkvh, (size_t)OC3 * HWN);

    // K2: depthwise 3x3, all channels, fp16->fp16, 8 px/thread
    dwconv_all<<<(BATCH * OC3 * HWN / 8) / 256, 256>>>(qkvh, dw_w, chd);

    // K3: tensor-core gram, cp.async double-buffered
    dim3 g3(32, BATCH * NHEADS);
    gram_tc<<<g3, 192, GRAM_SMEM>>>(chd, HWN / 32);

    // K4: softmax + fold proj
    attn_proj_kernel<<<BATCH, 256>>>(proj_w, temp);

    // K5: out = M_b @ v  (fp16 MMA, fp16 B in, fp32 C out)
    dim3 g5(2, HWN / (128 * NTILES), BATCH);
    gemm_f16<true, false><<<g5, 256, GEMM_SMEM>>>(Mp, (size_t)CDIM * CDIM, CDIM,
                                                  chd + (size_t)2 * CDIM * HWN, (size_t)OC3 * HWN,
                                                  out, (size_t)CDIM * HWN);
}

// round 13
// speedup vs baseline: 1.1155x; 1.0455x over previous
#include <cuda_runtime.h>
#include <cuda_fp16.h>
#include <stdint.h>
#include <math.h>

#define BATCH  4
#define CDIM   192
#define NHEADS 8
#define HDIM   24
#define HWN    65536
#define OC3    576
#define KDIM   192
#define NTILES 8
#define KPADH  200   // A row pad (halves)
#define NPADH  136   // B row pad (halves)

// ---- scratch (device globals) ----
__device__ __half g_qkvh[(size_t)BATCH * OC3 * HWN];  // 1x1-conv out, fp16
__device__ __half g_ch  [(size_t)BATCH * OC3 * HWN];  // dwconv out, fp16
__device__ float  g_g48 [BATCH * NHEADS * 48 * 48];   // [q;k] full gram
__device__ float  g_M   [BATCH * CDIM * CDIM];

__device__ __forceinline__ uint32_t smem_u32(const void* p) {
    uint32_t a;
    asm("{ .reg .u64 t; cvta.to.shared.u64 t, %1; cvt.u32.u64 %0, t; }" : "=r"(a) : "l"(p));
    return a;
}
__device__ __forceinline__ uint32_t h2u(__half2 h) { return *(uint32_t*)&h; }

#define LDSM_X4(r, addr) \
    asm volatile("ldmatrix.sync.aligned.m8n8.x4.shared.b16 {%0,%1,%2,%3}, [%4];" \
        : "=r"((r)[0]), "=r"((r)[1]), "=r"((r)[2]), "=r"((r)[3]) : "r"(addr))
#define LDSM_X4_T(r, addr) \
    asm volatile("ldmatrix.sync.aligned.m8n8.x4.trans.shared.b16 {%0,%1,%2,%3}, [%4];" \
        : "=r"((r)[0]), "=r"((r)[1]), "=r"((r)[2]), "=r"((r)[3]) : "r"(addr))
#define MMA_F16(cc, aa, b0, b1) \
    asm volatile("mma.sync.aligned.m16n8k16.row.col.f32.f16.f16.f32 " \
        "{%0,%1,%2,%3}, {%4,%5,%6,%7}, {%8,%9}, {%0,%1,%2,%3};" \
        : "+f"((cc)[0]), "+f"((cc)[1]), "+f"((cc)[2]), "+f"((cc)[3]) \
        : "r"((aa)[0]), "r"((aa)[1]), "r"((aa)[2]), "r"((aa)[3]), "r"(b0), "r"(b1))
#define CP_ASYNC16(dst, src) \
    asm volatile("cp.async.cg.shared.global [%0], [%1], 16;" :: "r"(dst), "l"(src) : "memory")
#define CP_COMMIT() asm volatile("cp.async.commit_group;" ::: "memory")
#define CP_WAIT(n)  asm volatile("cp.async.wait_group %0;" :: "n"(n) : "memory")

// ============================================================
// fp16 HMMA GEMM: C[b][m][n] = sum_k A[b][m][k] * B[b][k][n]
// (unchanged, validated)
// ============================================================
template<bool BH, bool OH>
__global__ __launch_bounds__(256) void gemm_f16(
    const float* __restrict__ A, size_t aStride, int Mreal,
    const void* __restrict__ Bv, size_t bStride,
    void* __restrict__ C, size_t cStride)
{
    extern __shared__ __half hsm[];
    __half* As  = hsm;                       // [128][KPADH]
    __half* Bs0 = As + 128 * KPADH;          // [64][NPADH]
    __half* Bs1 = Bs0 + 64 * NPADH;

    const float*  Bf = (const float*)Bv;
    const __half* Bh = (const __half*)Bv;
    float*  Cf = (float*)C;
    __half* Ch = (__half*)C;

    int tid  = threadIdx.x;
    int warp = tid >> 5, lane = tid & 31;
    int g = lane >> 2, t = lane & 3;
    int wm0 = (warp >> 1) * 32;
    int wn0 = (warp & 1) * 64;

    int m0    = blockIdx.x * 128;
    int b     = blockIdx.z;
    int nBase = blockIdx.y * (128 * NTILES);
    const float* Ab = A + (size_t)b * aStride;
    size_t bOff = (size_t)b * bStride;
    size_t cOff = (size_t)b * cStride;

    for (int it = tid; it < 128 * 48; it += 256) {
        int row = it / 48, c4 = (it - row * 48) * 4;
        float4 v = make_float4(0.f, 0.f, 0.f, 0.f);
        if (m0 + row < Mreal) v = *(const float4*)&Ab[(size_t)(m0 + row) * KDIM + c4];
        uint2 u;
        u.x = h2u(__float22half2_rn(make_float2(v.x, v.y)));
        u.y = h2u(__float22half2_rn(make_float2(v.z, v.w)));
        *(uint2*)(As + row * KPADH + c4) = u;
    }

    int kr  = tid >> 5;
    int lc4 = lane * 4;
    float4 pf[8];
    uint2  pf2[8];

    float c[2][8][4];
#pragma unroll
    for (int mt = 0; mt < 2; mt++)
#pragma unroll
        for (int nt = 0; nt < 8; nt++)
#pragma unroll
            for (int j = 0; j < 4; j++) c[mt][nt][j] = 0.f;

    const int TOT = NTILES * 3;
    uint32_t sA  = smem_u32(As);
    uint32_t sB0 = smem_u32(Bs0);
    uint32_t sB1 = smem_u32(Bs1);

    {
        if (BH) {
#pragma unroll
            for (int j = 0; j < 8; j++)
                pf2[j] = *(const uint2*)&Bh[bOff + (size_t)(kr + 8 * j) * HWN + nBase + lc4];
        } else {
#pragma unroll
            for (int j = 0; j < 8; j++)
                pf[j] = *(const float4*)&Bf[bOff + (size_t)(kr + 8 * j) * HWN + nBase + lc4];
        }
#pragma unroll
        for (int j = 0; j < 8; j++) {
            uint2 u;
            if (BH) u = pf2[j];
            else {
                u.x = h2u(__float22half2_rn(make_float2(pf[j].x, pf[j].y)));
                u.y = h2u(__float22half2_rn(make_float2(pf[j].z, pf[j].w)));
            }
            *(uint2*)(Bs0 + (kr + 8 * j) * NPADH + lc4) = u;
        }
    }
    __syncthreads();

    for (int i = 0; i < TOT; i++) {
        int tile = i / 3;
        int kc   = i - tile * 3;

        if (i + 1 < TOT) {
            int ntile = (i + 1) / 3;
            int nkc   = (i + 1) - ntile * 3;
            size_t src = bOff + (size_t)(nkc * 64 + kr) * HWN + nBase + ntile * 128 + lc4;
            if (BH) {
#pragma unroll
                for (int j = 0; j < 8; j++) pf2[j] = *(const uint2*)&Bh[src + (size_t)j * 8 * HWN];
            } else {
#pragma unroll
                for (int j = 0; j < 8; j++) pf[j] = *(const float4*)&Bf[src + (size_t)j * 8 * HWN];
            }
        }

        uint32_t sB = (i & 1) ? sB1 : sB0;
#pragma unroll
        for (int ks = 0; ks < 4; ks++) {
            uint32_t a[2][4];
            int kA = kc * 64 + ks * 16 + ((lane >> 4) << 3);
#pragma unroll
            for (int mt = 0; mt < 2; mt++) {
                int row = wm0 + mt * 16 + (lane & 15);
                LDSM_X4(a[mt], sA + (uint32_t)(row * KPADH + kA) * 2);
            }
#pragma unroll
            for (int pr = 0; pr < 4; pr++) {
                uint32_t bq[4];
                int brow = ks * 16 + (lane & 15);
                int bcol = wn0 + pr * 16 + ((lane >> 4) << 3);
                LDSM_X4_T(bq, sB + (uint32_t)(brow * NPADH + bcol) * 2);
                MMA_F16(c[0][2 * pr],     a[0], bq[0], bq[1]);
                MMA_F16(c[1][2 * pr],     a[1], bq[0], bq[1]);
                MMA_F16(c[0][2 * pr + 1], a[0], bq[2], bq[3]);
                MMA_F16(c[1][2 * pr + 1], a[1], bq[2], bq[3]);
            }
        }

        if (kc == 2) {
            int n0 = nBase + tile * 128;
#pragma unroll
            for (int mt = 0; mt < 2; mt++) {
                int row0 = m0 + wm0 + mt * 16 + g;
#pragma unroll
                for (int nt = 0; nt < 8; nt++) {
                    int col = n0 + wn0 + nt * 8 + 2 * t;
                    if (row0 < Mreal) {
                        if (OH) *(__half2*)&Ch[cOff + (size_t)row0 * HWN + col] =
                            __floats2half2_rn(c[mt][nt][0], c[mt][nt][1]);
                        else {
                            float2 v = {c[mt][nt][0], c[mt][nt][1]};
                            *(float2*)&Cf[cOff + (size_t)row0 * HWN + col] = v;
                        }
                    }
                    if (row0 + 8 < Mreal) {
                        if (OH) *(__half2*)&Ch[cOff + (size_t)(row0 + 8) * HWN + col] =
                            __floats2half2_rn(c[mt][nt][2], c[mt][nt][3]);
                        else {
                            float2 v = {c[mt][nt][2], c[mt][nt][3]};
                            *(float2*)&Cf[cOff + (size_t)(row0 + 8) * HWN + col] = v;
                        }
                    }
                    c[mt][nt][0] = 0.f; c[mt][nt][1] = 0.f;
                    c[mt][nt][2] = 0.f; c[mt][nt][3] = 0.f;
                }
            }
        }

        if (i + 1 < TOT) {
            __half* nbuf = (i & 1) ? Bs0 : Bs1;
#pragma unroll
            for (int j = 0; j < 8; j++) {
                uint2 u;
                if (BH) u = pf2[j];
                else {
                    u.x = h2u(__float22half2_rn(make_float2(pf[j].x, pf[j].y)));
                    u.y = h2u(__float22half2_rn(make_float2(pf[j].z, pf[j].w)));
                }
                *(uint2*)(nbuf + (kr + 8 * j) * NPADH + lc4) = u;
            }
            __syncthreads();
        }
    }
}

// ============================================================
// depthwise 3x3, fp16 in/out, 8 px/thread; halos via warp shuffle
// (each warp = one full 256-px image row)
// ============================================================
__global__ __launch_bounds__(256) void dwconv_all(
    const __half* __restrict__ in, const float* __restrict__ wAll,
    __half* __restrict__ out)
{
    int idx = blockIdx.x * 256 + threadIdx.x;
    int p8 = idx & 8191;
    int bc = idx >> 13;
    int ch = bc % OC3;
    int y  = p8 >> 5;
    int lane = threadIdx.x & 31;          // == p8 & 31 (alignment)
    int x0 = lane << 3;
    const __half* base = in + (size_t)bc * HWN;

    float w[9];
#pragma unroll
    for (int i = 0; i < 9; i++) w[i] = __ldg(&wAll[ch * 9 + i]);

    uint4 rowv[3];
    bool ok[3];
#pragma unroll
    for (int ky = 0; ky < 3; ky++) {
        int yy = y + ky - 1;
        ok[ky] = ((unsigned)yy < 256u);
        if (ok[ky]) rowv[ky] = *(const uint4*)&base[yy * 256 + x0];
    }

    float s[8];
#pragma unroll
    for (int o = 0; o < 8; o++) s[o] = 0.f;

#pragma unroll
    for (int ky = 0; ky < 3; ky++) {
        float f[10];
        const __half* hp = (const __half*)&rowv[ky];
#pragma unroll
        for (int j = 0; j < 8; j++) f[j + 1] = __half2float(hp[j]);
        // halos from neighbor lanes (ok[] is warp-uniform; shfl full-warp)
        float l = __shfl_up_sync(0xffffffffu, f[8], 1);
        float r = __shfl_down_sync(0xffffffffu, f[1], 1);
        f[0] = (lane == 0)  ? 0.f : l;
        f[9] = (lane == 31) ? 0.f : r;
        if (!ok[ky]) continue;
        float w0 = w[ky * 3], w1 = w[ky * 3 + 1], w2 = w[ky * 3 + 2];
#pragma unroll
        for (int o = 0; o < 8; o++)
            s[o] += f[o] * w0 + f[o + 1] * w1 + f[o + 2] * w2;
    }

    uint4 u;
    u.x = h2u(__floats2half2_rn(s[0], s[1]));
    u.y = h2u(__floats2half2_rn(s[2], s[3]));
    u.z = h2u(__floats2half2_rn(s[4], s[5]));
    u.w = h2u(__floats2half2_rn(s[6], s[7]));
    *(uint4*)&out[(size_t)idx * 8] = u;
}

__global__ void zero_g48() {
    int i = blockIdx.x * blockDim.x + threadIdx.x;
    if (i < BATCH * NHEADS * 48 * 48) g_g48[i] = 0.f;
}

// ============================================================
// Tensor-core gram v5: 3-stage cp.async pipeline, 256-px tiles.
// 192 threads = 6 warps = 2 pixel-halves (128 px) x 3 m-tiles.
// ============================================================
#define GTPAD 264     // 528 B rows: conflict-free ldmatrix
__global__ __launch_bounds__(192) void gram_tc(const __half* __restrict__ chd, int pxPer)
{
    extern __shared__ __half gsm[];          // [3][48][GTPAD]
    int bh = blockIdx.y;
    int b = bh >> 3, hh = bh & 7;
    int tid = threadIdx.x;
    int warp = tid >> 5, lane = tid & 31;
    int half = warp / 3;
    int mt   = warp - half * 3;
    int m0 = mt * 16;
    int colBase = half * 128;

    int lrow = tid >> 2;                 // 0..47
    int lseg0 = (tid & 3) * 8;           // 8 consecutive uint4 segs
    int lgch = (lrow < 24) ? (hh * HDIM + lrow) : (CDIM + hh * HDIM + (lrow - 24));
    const __half* lsrc = chd + ((size_t)b * OC3 + lgch) * HWN;

    float c[6][4];
#pragma unroll
    for (int nt = 0; nt < 6; nt++)
#pragma unroll
        for (int j = 0; j < 4; j++) c[nt][j] = 0.f;

    int aRow = m0 + (lane & 15);
    int aK   = colBase + ((lane >> 4) << 3);
    int bRowLoc = ((lane >> 4) << 3) + (lane & 7);
    int bK      = colBase + (((lane >> 3) & 1) << 3);

    uint32_t sbuf[3];
    sbuf[0] = smem_u32(gsm);
    sbuf[1] = sbuf[0] + 48 * GTPAD * 2;
    sbuf[2] = sbuf[1] + 48 * GTPAD * 2;
    uint32_t rowOff = (uint32_t)(lrow * GTPAD) * 2;

    int nStart = blockIdx.x * pxPer;
    int nIters = pxPer / 256;

    // prologue: tiles 0,1
#pragma unroll
    for (int p = 0; p < 2; p++) {
        const __half* src = lsrc + nStart + p * 256;
        uint32_t d = sbuf[p] + rowOff;
#pragma unroll
        for (int j = 0; j < 8; j++)
            CP_ASYNC16(d + (uint32_t)((lseg0 + j) * 8) * 2, src + (lseg0 + j) * 8);
        CP_COMMIT();
    }

    for (int it = 0; it < nIters; it++) {
        if (it + 2 < nIters) {
            const __half* src = lsrc + nStart + (it + 2) * 256;
            uint32_t d = sbuf[(it + 2) % 3] + rowOff;
#pragma unroll
            for (int j = 0; j < 8; j++)
                CP_ASYNC16(d + (uint32_t)((lseg0 + j) * 8) * 2, src + (lseg0 + j) * 8);
            CP_COMMIT();
            CP_WAIT(2);
        } else if (it + 1 < nIters) {
            CP_WAIT(1);
        } else {
            CP_WAIT(0);
        }
        __syncthreads();

        uint32_t sB = sbuf[it % 3];
        uint32_t aAddr = sB + (uint32_t)(aRow * GTPAD + aK) * 2;
#pragma unroll
        for (int ks = 0; ks < 8; ks++) {
            uint32_t a[4];
            LDSM_X4(a, aAddr + (uint32_t)(ks * 16) * 2);
#pragma unroll
            for (int nb = 0; nb < 3; nb++) {
                uint32_t bq[4];
                int nr = nb * 16 + bRowLoc;
                LDSM_X4(bq, sB + (uint32_t)(nr * GTPAD + bK + ks * 16) * 2);
                MMA_F16(c[2 * nb],     a, bq[0], bq[1]);
                MMA_F16(c[2 * nb + 1], a, bq[2], bq[3]);
            }
        }
        __syncthreads();   // reads of buf[it%3] done before iter it+1 overwrites
    }

    float* gb = &g_g48[bh * 2304];
    int gm = lane >> 2, gt2 = (lane & 3) * 2;
#pragma unroll
    for (int nt = 0; nt < 6; nt++) {
        int col = nt * 8 + gt2;
        atomicAdd(&gb[(m0 + gm) * 48 + col],     c[nt][0]);
        atomicAdd(&gb[(m0 + gm) * 48 + col + 1], c[nt][1]);
        atomicAdd(&gb[(m0 + gm + 8) * 48 + col],     c[nt][2]);
        atomicAdd(&gb[(m0 + gm + 8) * 48 + col + 1], c[nt][3]);
    }
}

// ============================================================
// softmax + fold proj -> per-batch M (fp32)
// ============================================================
__global__ __launch_bounds__(256) void attn_proj_kernel(
    const float* __restrict__ projw, const float* __restrict__ temp)
{
    __shared__ float attn_s[NHEADS * HDIM * HDIM];
    int b = blockIdx.x;
    int t = threadIdx.x;
    if (t < CDIM) {
        int hh = t / HDIM, d = t % HDIM;
        const float* G = &g_g48[(b * NHEADS + hh) * 2304];
        float nq = fmaxf(sqrtf(G[d * 48 + d]), 1e-12f);
        float tm = temp[hh];
        float row[HDIM];
        float mx = -1e30f;
#pragma unroll
        for (int e = 0; e < HDIM; e++) {
            float nk = fmaxf(sqrtf(G[(24 + e) * 48 + 24 + e]), 1e-12f);
            float a = G[d * 48 + 24 + e] / (nq * nk) * tm;
            row[e] = a; mx = fmaxf(mx, a);
        }
        float s = 0.f;
#pragma unroll
        for (int e = 0; e < HDIM; e++) { row[e] = expf(row[e] - mx); s += row[e]; }
        float inv = 1.f / s;
#pragma unroll
        for (int e = 0; e < HDIM; e++) attn_s[hh * 576 + d * 24 + e] = row[e] * inv;
    }
    __syncthreads();
    if (t < CDIM) {
        int o = t;
        const float* pr = &projw[o * CDIM];
        for (int hh = 0; hh < NHEADS; hh++) {
#pragma unroll
            for (int e = 0; e < HDIM; e++) {
                float acc = 0.f;
#pragma unroll
                for (int d = 0; d < HDIM; d++)
                    acc += pr[hh * 24 + d] * attn_s[hh * 576 + d * 24 + e];
                g_M[((size_t)b * CDIM + o) * CDIM + hh * 24 + e] = acc;
            }
        }
    }
}

// ============================================================
extern "C" void kernel_launch(void* const* d_in, const int* in_sizes, int n_in,
                              void* d_out, int out_size)
{
    const float* x      = (const float*)d_in[0];
    const float* qkv_w  = (const float*)d_in[1];
    const float* dw_w   = (const float*)d_in[2];
    const float* proj_w = (const float*)d_in[3];
    const float* temp   = (const float*)d_in[4];
    float* out = (float*)d_out;

    __half *qkvh, *chd;
    float *Mp;
    cudaGetSymbolAddress((void**)&qkvh, g_qkvh);
    cudaGetSymbolAddress((void**)&chd,  g_ch);
    cudaGetSymbolAddress((void**)&Mp,   g_M);

    const int GEMM_SMEM = (128 * KPADH + 2 * 64 * NPADH) * 2;
    const int GRAM_SMEM = 3 * 48 * GTPAD * 2;
    cudaFuncSetAttribute(gemm_f16<false, true>, cudaFuncAttributeMaxDynamicSharedMemorySize, GEMM_SMEM);
    cudaFuncSetAttribute(gemm_f16<true, false>, cudaFuncAttributeMaxDynamicSharedMemorySize, GEMM_SMEM);
    cudaFuncSetAttribute(gram_tc, cudaFuncAttributeMaxDynamicSharedMemorySize, GRAM_SMEM);

    zero_g48<<<(BATCH * NHEADS * 2304 + 255) / 256, 256>>>();

    // K1: qkv = W_qkv @ x  (fp16 MMA, fp32 B in, fp16 C out)
    dim3 g1(5, HWN / (128 * NTILES), BATCH);
    gemm_f16<false, true><<<g1, 256, GEMM_SMEM>>>(qkv_w, 0, OC3,
                                                  x, (size_t)CDIM * HWN,
                                                  qkvh, (size_t)OC3 * HWN);

    // K2: depthwise 3x3, shfl halos
    dwconv_all<<<(BATCH * OC3 * HWN / 8) / 256, 256>>>(qkvh, dw_w, chd);

    // K3: tensor-core gram, 3-stage cp.async
    dim3 g3(32, BATCH * NHEADS);
    gram_tc<<<g3, 192, GRAM_SMEM>>>(chd, HWN / 32);

    // K4: softmax + fold proj
    attn_proj_kernel<<<BATCH, 256>>>(proj_w, temp);

    // K5: out = M_b @ v  (fp16 MMA, fp16 B in, fp32 C out)
    dim3 g5(2, HWN / (128 * NTILES), BATCH);
    gemm_f16<true, false><<<g5, 256, GEMM_SMEM>>>(Mp, (size_t)CDIM * CDIM, CDIM,
                                                  chd + (size_t)2 * CDIM * HWN, (size_t)OC3 * HWN,
                                                  out, (size_t)CDIM * HWN);
}

// round 14
// speedup vs baseline: 1.1656x; 1.0449x over previous
#include <cuda_runtime.h>
#include <cuda_fp16.h>
#include <stdint.h>
#include <math.h>

#define BATCH  4
#define CDIM   192
#define NHEADS 8
#define HDIM   24
#define HWN    65536
#define OC3    576
#define KDIM   192
#define NTILES 8
#define KPADH  200   // A row pad (halves)
#define NPADH  136   // B row pad (halves)

// ---- scratch (device globals; zero-initialized at module load) ----
__device__ __half g_qkvh[(size_t)BATCH * OC3 * HWN];  // 1x1-conv out, fp16
__device__ __half g_ch  [(size_t)BATCH * OC3 * HWN];  // dwconv out, fp16
__device__ float  g_g48 [BATCH * NHEADS * 48 * 48];   // [q;k] full gram (re-zeroed by attn_proj)
__device__ float  g_M   [BATCH * CDIM * CDIM];

__device__ __forceinline__ uint32_t smem_u32(const void* p) {
    uint32_t a;
    asm("{ .reg .u64 t; cvta.to.shared.u64 t, %1; cvt.u32.u64 %0, t; }" : "=r"(a) : "l"(p));
    return a;
}
__device__ __forceinline__ uint32_t h2u(__half2 h) { return *(uint32_t*)&h; }

#define LDSM_X4(r, addr) \
    asm volatile("ldmatrix.sync.aligned.m8n8.x4.shared.b16 {%0,%1,%2,%3}, [%4];" \
        : "=r"((r)[0]), "=r"((r)[1]), "=r"((r)[2]), "=r"((r)[3]) : "r"(addr))
#define LDSM_X4_T(r, addr) \
    asm volatile("ldmatrix.sync.aligned.m8n8.x4.trans.shared.b16 {%0,%1,%2,%3}, [%4];" \
        : "=r"((r)[0]), "=r"((r)[1]), "=r"((r)[2]), "=r"((r)[3]) : "r"(addr))
#define MMA_F16(cc, aa, b0, b1) \
    asm volatile("mma.sync.aligned.m16n8k16.row.col.f32.f16.f16.f32 " \
        "{%0,%1,%2,%3}, {%4,%5,%6,%7}, {%8,%9}, {%0,%1,%2,%3};" \
        : "+f"((cc)[0]), "+f"((cc)[1]), "+f"((cc)[2]), "+f"((cc)[3]) \
        : "r"((aa)[0]), "r"((aa)[1]), "r"((aa)[2]), "r"((aa)[3]), "r"(b0), "r"(b1))
#define CP_ASYNC16(dst, src) \
    asm volatile("cp.async.cg.shared.global [%0], [%1], 16;" :: "r"(dst), "l"(src) : "memory")
#define CP_COMMIT() asm volatile("cp.async.commit_group;" ::: "memory")
#define CP_WAIT(n)  asm volatile("cp.async.wait_group %0;" :: "n"(n) : "memory")

// ============================================================
// fp16 HMMA GEMM: C[b][m][n] = sum_k A[b][m][k] * B[b][k][n]
// (unchanged, validated)
// ============================================================
template<bool BH, bool OH>
__global__ __launch_bounds__(256) void gemm_f16(
    const float* __restrict__ A, size_t aStride, int Mreal,
    const void* __restrict__ Bv, size_t bStride,
    void* __restrict__ C, size_t cStride)
{
    extern __shared__ __half hsm[];
    __half* As  = hsm;                       // [128][KPADH]
    __half* Bs0 = As + 128 * KPADH;          // [64][NPADH]
    __half* Bs1 = Bs0 + 64 * NPADH;

    const float*  Bf = (const float*)Bv;
    const __half* Bh = (const __half*)Bv;
    float*  Cf = (float*)C;
    __half* Ch = (__half*)C;

    int tid  = threadIdx.x;
    int warp = tid >> 5, lane = tid & 31;
    int g = lane >> 2, t = lane & 3;
    int wm0 = (warp >> 1) * 32;
    int wn0 = (warp & 1) * 64;

    int m0    = blockIdx.x * 128;
    int b     = blockIdx.z;
    int nBase = blockIdx.y * (128 * NTILES);
    const float* Ab = A + (size_t)b * aStride;
    size_t bOff = (size_t)b * bStride;
    size_t cOff = (size_t)b * cStride;

    for (int it = tid; it < 128 * 48; it += 256) {
        int row = it / 48, c4 = (it - row * 48) * 4;
        float4 v = make_float4(0.f, 0.f, 0.f, 0.f);
        if (m0 + row < Mreal) v = *(const float4*)&Ab[(size_t)(m0 + row) * KDIM + c4];
        uint2 u;
        u.x = h2u(__float22half2_rn(make_float2(v.x, v.y)));
        u.y = h2u(__float22half2_rn(make_float2(v.z, v.w)));
        *(uint2*)(As + row * KPADH + c4) = u;
    }

    int kr  = tid >> 5;
    int lc4 = lane * 4;
    float4 pf[8];
    uint2  pf2[8];

    float c[2][8][4];
#pragma unroll
    for (int mt = 0; mt < 2; mt++)
#pragma unroll
        for (int nt = 0; nt < 8; nt++)
#pragma unroll
            for (int j = 0; j < 4; j++) c[mt][nt][j] = 0.f;

    const int TOT = NTILES * 3;
    uint32_t sA  = smem_u32(As);
    uint32_t sB0 = smem_u32(Bs0);
    uint32_t sB1 = smem_u32(Bs1);

    {
        if (BH) {
#pragma unroll
            for (int j = 0; j < 8; j++)
                pf2[j] = *(const uint2*)&Bh[bOff + (size_t)(kr + 8 * j) * HWN + nBase + lc4];
        } else {
#pragma unroll
            for (int j = 0; j < 8; j++)
                pf[j] = *(const float4*)&Bf[bOff + (size_t)(kr + 8 * j) * HWN + nBase + lc4];
        }
#pragma unroll
        for (int j = 0; j < 8; j++) {
            uint2 u;
            if (BH) u = pf2[j];
            else {
                u.x = h2u(__float22half2_rn(make_float2(pf[j].x, pf[j].y)));
                u.y = h2u(__float22half2_rn(make_float2(pf[j].z, pf[j].w)));
            }
            *(uint2*)(Bs0 + (kr + 8 * j) * NPADH + lc4) = u;
        }
    }
    __syncthreads();

    for (int i = 0; i < TOT; i++) {
        int tile = i / 3;
        int kc   = i - tile * 3;

        if (i + 1 < TOT) {
            int ntile = (i + 1) / 3;
            int nkc   = (i + 1) - ntile * 3;
            size_t src = bOff + (size_t)(nkc * 64 + kr) * HWN + nBase + ntile * 128 + lc4;
            if (BH) {
#pragma unroll
                for (int j = 0; j < 8; j++) pf2[j] = *(const uint2*)&Bh[src + (size_t)j * 8 * HWN];
            } else {
#pragma unroll
                for (int j = 0; j < 8; j++) pf[j] = *(const float4*)&Bf[src + (size_t)j * 8 * HWN];
            }
        }

        uint32_t sB = (i & 1) ? sB1 : sB0;
#pragma unroll
        for (int ks = 0; ks < 4; ks++) {
            uint32_t a[2][4];
            int kA = kc * 64 + ks * 16 + ((lane >> 4) << 3);
#pragma unroll
            for (int mt = 0; mt < 2; mt++) {
                int row = wm0 + mt * 16 + (lane & 15);
                LDSM_X4(a[mt], sA + (uint32_t)(row * KPADH + kA) * 2);
            }
#pragma unroll
            for (int pr = 0; pr < 4; pr++) {
                uint32_t bq[4];
                int brow = ks * 16 + (lane & 15);
                int bcol = wn0 + pr * 16 + ((lane >> 4) << 3);
                LDSM_X4_T(bq, sB + (uint32_t)(brow * NPADH + bcol) * 2);
                MMA_F16(c[0][2 * pr],     a[0], bq[0], bq[1]);
                MMA_F16(c[1][2 * pr],     a[1], bq[0], bq[1]);
                MMA_F16(c[0][2 * pr + 1], a[0], bq[2], bq[3]);
                MMA_F16(c[1][2 * pr + 1], a[1], bq[2], bq[3]);
            }
        }

        if (kc == 2) {
            int n0 = nBase + tile * 128;
#pragma unroll
            for (int mt = 0; mt < 2; mt++) {
                int row0 = m0 + wm0 + mt * 16 + g;
#pragma unroll
                for (int nt = 0; nt < 8; nt++) {
                    int col = n0 + wn0 + nt * 8 + 2 * t;
                    if (row0 < Mreal) {
                        if (OH) *(__half2*)&Ch[cOff + (size_t)row0 * HWN + col] =
                            __floats2half2_rn(c[mt][nt][0], c[mt][nt][1]);
                        else {
                            float2 v = {c[mt][nt][0], c[mt][nt][1]};
                            *(float2*)&Cf[cOff + (size_t)row0 * HWN + col] = v;
                        }
                    }
                    if (row0 + 8 < Mreal) {
                        if (OH) *(__half2*)&Ch[cOff + (size_t)(row0 + 8) * HWN + col] =
                            __floats2half2_rn(c[mt][nt][2], c[mt][nt][3]);
                        else {
                            float2 v = {c[mt][nt][2], c[mt][nt][3]};
                            *(float2*)&Cf[cOff + (size_t)(row0 + 8) * HWN + col] = v;
                        }
                    }
                    c[mt][nt][0] = 0.f; c[mt][nt][1] = 0.f;
                    c[mt][nt][2] = 0.f; c[mt][nt][3] = 0.f;
                }
            }
        }

        if (i + 1 < TOT) {
            __half* nbuf = (i & 1) ? Bs0 : Bs1;
#pragma unroll
            for (int j = 0; j < 8; j++) {
                uint2 u;
                if (BH) u = pf2[j];
                else {
                    u.x = h2u(__float22half2_rn(make_float2(pf[j].x, pf[j].y)));
                    u.y = h2u(__float22half2_rn(make_float2(pf[j].z, pf[j].w)));
                }
                *(uint2*)(nbuf + (kr + 8 * j) * NPADH + lc4) = u;
            }
            __syncthreads();
        }
    }
}

// ============================================================
// depthwise 3x3: 2 output rows x 8 px per thread, vertical reuse.
// Halos via warp shuffle (warp = one 256-px row pair).
// ============================================================
__global__ __launch_bounds__(256) void dwconv_all(
    const __half* __restrict__ in, const float* __restrict__ wAll,
    __half* __restrict__ out)
{
    int idx = blockIdx.x * 256 + threadIdx.x;   // over BATCH*OC3*HWN/16
    int p16 = idx & 4095;
    int bc  = idx >> 12;
    int ch  = bc % OC3;
    int y   = (p16 >> 5) * 2;                   // even row 0..254
    int lane = threadIdx.x & 31;                // == p16 & 31
    int x0 = lane << 3;
    const __half* base = in + (size_t)bc * HWN;

    float w[9];
#pragma unroll
    for (int i = 0; i < 9; i++) w[i] = __ldg(&wAll[ch * 9 + i]);

    // rows y-1, y, y+1, y+2 (warp-uniform validity)
    uint4 rowv[4];
    bool ok[4];
#pragma unroll
    for (int r = 0; r < 4; r++) {
        int yy = y + r - 1;
        ok[r] = ((unsigned)yy < 256u);
        if (ok[r]) rowv[r] = *(const uint4*)&base[yy * 256 + x0];
    }

    float f[4][10];
#pragma unroll
    for (int r = 0; r < 4; r++) {
        const __half* hp = (const __half*)&rowv[r];
#pragma unroll
        for (int j = 0; j < 8; j++) f[r][j + 1] = __half2float(hp[j]);
        float l = __shfl_up_sync(0xffffffffu, f[r][8], 1);
        float rr = __shfl_down_sync(0xffffffffu, f[r][1], 1);
        f[r][0] = (lane == 0)  ? 0.f : l;
        f[r][9] = (lane == 31) ? 0.f : rr;
    }

    float s0[8], s1[8];
#pragma unroll
    for (int o = 0; o < 8; o++) { s0[o] = 0.f; s1[o] = 0.f; }

#pragma unroll
    for (int kr = 0; kr < 3; kr++) {
        float w0 = w[kr * 3], w1 = w[kr * 3 + 1], w2 = w[kr * 3 + 2];
        // output row y uses input rows kr (index kr in f)
        if (ok[kr]) {
#pragma unroll
            for (int o = 0; o < 8; o++)
                s0[o] += f[kr][o] * w0 + f[kr][o + 1] * w1 + f[kr][o + 2] * w2;
        }
        // output row y+1 uses input rows kr+1
        if (ok[kr + 1]) {
#pragma unroll
            for (int o = 0; o < 8; o++)
                s1[o] += f[kr + 1][o] * w0 + f[kr + 1][o + 1] * w1 + f[kr + 1][o + 2] * w2;
        }
    }

    __half* obase = out + (size_t)bc * HWN;
    uint4 u0, u1;
    u0.x = h2u(__floats2half2_rn(s0[0], s0[1]));
    u0.y = h2u(__floats2half2_rn(s0[2], s0[3]));
    u0.z = h2u(__floats2half2_rn(s0[4], s0[5]));
    u0.w = h2u(__floats2half2_rn(s0[6], s0[7]));
    u1.x = h2u(__floats2half2_rn(s1[0], s1[1]));
    u1.y = h2u(__floats2half2_rn(s1[2], s1[3]));
    u1.z = h2u(__floats2half2_rn(s1[4], s1[5]));
    u1.w = h2u(__floats2half2_rn(s1[6], s1[7]));
    *(uint4*)&obase[y * 256 + x0]       = u0;
    *(uint4*)&obase[(y + 1) * 256 + x0] = u1;
}

// ============================================================
// Tensor-core gram (validated 2-stage cp.async, 256-px tiles).
// 192 threads = 6 warps = 2 pixel-halves (128 px) x 3 m-tiles.
// ============================================================
#define GTPAD 264     // 528 B rows: conflict-free ldmatrix
__global__ __launch_bounds__(192) void gram_tc(const __half* __restrict__ chd, int pxPer)
{
    extern __shared__ __half gsm[];          // [2][48][GTPAD]
    __half* buf0 = gsm;
    __half* buf1 = gsm + 48 * GTPAD;

    int bh = blockIdx.y;
    int b = bh >> 3, hh = bh & 7;
    int tid = threadIdx.x;
    int warp = tid >> 5, lane = tid & 31;
    int half = warp / 3;
    int mt   = warp - half * 3;
    int m0 = mt * 16;
    int colBase = half * 128;

    int lrow = tid >> 2;                 // 0..47
    int lseg0 = (tid & 3) * 8;           // 8 consecutive uint4 segs
    int lgch = (lrow < 24) ? (hh * HDIM + lrow) : (CDIM + hh * HDIM + (lrow - 24));
    const __half* lsrc = chd + ((size_t)b * OC3 + lgch) * HWN;

    float c[6][4];
#pragma unroll
    for (int nt = 0; nt < 6; nt++)
#pragma unroll
        for (int j = 0; j < 4; j++) c[nt][j] = 0.f;

    int aRow = m0 + (lane & 15);
    int aK   = colBase + ((lane >> 4) << 3);
    int bRowLoc = ((lane >> 4) << 3) + (lane & 7);
    int bK      = colBase + (((lane >> 3) & 1) << 3);
    uint32_t sb0 = smem_u32(buf0);
    uint32_t sb1 = smem_u32(buf1);
    uint32_t dRow0 = sb0 + (uint32_t)(lrow * GTPAD) * 2;
    uint32_t dRow1 = sb1 + (uint32_t)(lrow * GTPAD) * 2;

    int nStart = blockIdx.x * pxPer;
    int nIters = pxPer / 256;

    {   // prologue: tile 0
        const __half* src = lsrc + nStart;
#pragma unroll
        for (int j = 0; j < 8; j++)
            CP_ASYNC16(dRow0 + (uint32_t)((lseg0 + j) * 8) * 2, src + (lseg0 + j) * 8);
        CP_COMMIT();
    }

    for (int it = 0; it < nIters; it++) {
        if (it + 1 < nIters) {
            const __half* src = lsrc + nStart + (it + 1) * 256;
            uint32_t d = ((it + 1) & 1) ? dRow1 : dRow0;
#pragma unroll
            for (int j = 0; j < 8; j++)
                CP_ASYNC16(d + (uint32_t)((lseg0 + j) * 8) * 2, src + (lseg0 + j) * 8);
            CP_COMMIT();
            CP_WAIT(1);
        } else {
            CP_WAIT(0);
        }
        __syncthreads();

        uint32_t sB = (it & 1) ? sb1 : sb0;
        uint32_t aAddr = sB + (uint32_t)(aRow * GTPAD + aK) * 2;
#pragma unroll
        for (int ks = 0; ks < 8; ks++) {
            uint32_t a[4];
            LDSM_X4(a, aAddr + (uint32_t)(ks * 16) * 2);
#pragma unroll
            for (int nb = 0; nb < 3; nb++) {
                uint32_t bq[4];
                int nr = nb * 16 + bRowLoc;
                LDSM_X4(bq, sB + (uint32_t)(nr * GTPAD + bK + ks * 16) * 2);
                MMA_F16(c[2 * nb],     a, bq[0], bq[1]);
                MMA_F16(c[2 * nb + 1], a, bq[2], bq[3]);
            }
        }
        __syncthreads();
    }

    float* gb = &g_g48[bh * 2304];
    int gm = lane >> 2, gt2 = (lane & 3) * 2;
#pragma unroll
    for (int nt = 0; nt < 6; nt++) {
        int col = nt * 8 + gt2;
        atomicAdd(&gb[(m0 + gm) * 48 + col],     c[nt][0]);
        atomicAdd(&gb[(m0 + gm) * 48 + col + 1], c[nt][1]);
        atomicAdd(&gb[(m0 + gm + 8) * 48 + col],     c[nt][2]);
        atomicAdd(&gb[(m0 + gm + 8) * 48 + col + 1], c[nt][3]);
    }
}

// ============================================================
// softmax + fold proj -> per-batch M; then re-zero g48 for next replay
// ============================================================
__global__ __launch_bounds__(256) void attn_proj_kernel(
    const float* __restrict__ projw, const float* __restrict__ temp)
{
    __shared__ float attn_s[NHEADS * HDIM * HDIM];
    int b = blockIdx.x;
    int t = threadIdx.x;
    if (t < CDIM) {
        int hh = t / HDIM, d = t % HDIM;
        const float* G = &g_g48[(b * NHEADS + hh) * 2304];
        float nq = fmaxf(sqrtf(G[d * 48 + d]), 1e-12f);
        float tm = temp[hh];
        float row[HDIM];
        float mx = -1e30f;
#pragma unroll
        for (int e = 0; e < HDIM; e++) {
            float nk = fmaxf(sqrtf(G[(24 + e) * 48 + 24 + e]), 1e-12f);
            float a = G[d * 48 + 24 + e] / (nq * nk) * tm;
            row[e] = a; mx = fmaxf(mx, a);
        }
        float s = 0.f;
#pragma unroll
        for (int e = 0; e < HDIM; e++) { row[e] = expf(row[e] - mx); s += row[e]; }
        float inv = 1.f / s;
#pragma unroll
        for (int e = 0; e < HDIM; e++) attn_s[hh * 576 + d * 24 + e] = row[e] * inv;
    }
    __syncthreads();   // all g48 reads for this batch complete past this point
    if (t < CDIM) {
        int o = t;
        const float* pr = &projw[o * CDIM];
        for (int hh = 0; hh < NHEADS; hh++) {
#pragma unroll
            for (int e = 0; e < HDIM; e++) {
                float acc = 0.f;
#pragma unroll
                for (int d = 0; d < HDIM; d++)
                    acc += pr[hh * 24 + d] * attn_s[hh * 576 + d * 24 + e];
                g_M[((size_t)b * CDIM + o) * CDIM + hh * 24 + e] = acc;
            }
        }
    }
    // re-zero this batch's gram region for the next graph replay
    for (int i = t; i < NHEADS * 2304; i += 256)
        g_g48[b * NHEADS * 2304 + i] = 0.f;
}

// ============================================================
extern "C" void kernel_launch(void* const* d_in, const int* in_sizes, int n_in,
                              void* d_out, int out_size)
{
    const float* x      = (const float*)d_in[0];
    const float* qkv_w  = (const float*)d_in[1];
    const float* dw_w   = (const float*)d_in[2];
    const float* proj_w = (const float*)d_in[3];
    const float* temp   = (const float*)d_in[4];
    float* out = (float*)d_out;

    __half *qkvh, *chd;
    float *Mp;
    cudaGetSymbolAddress((void**)&qkvh, g_qkvh);
    cudaGetSymbolAddress((void**)&chd,  g_ch);
    cudaGetSymbolAddress((void**)&Mp,   g_M);

    const int GEMM_SMEM = (128 * KPADH + 2 * 64 * NPADH) * 2;
    const int GRAM_SMEM = 2 * 48 * GTPAD * 2;
    cudaFuncSetAttribute(gemm_f16<false, true>, cudaFuncAttributeMaxDynamicSharedMemorySize, GEMM_SMEM);
    cudaFuncSetAttribute(gemm_f16<true, false>, cudaFuncAttributeMaxDynamicSharedMemorySize, GEMM_SMEM);
    cudaFuncSetAttribute(gram_tc, cudaFuncAttributeMaxDynamicSharedMemorySize, GRAM_SMEM);

    // K1: qkv = W_qkv @ x  (fp16 MMA, fp32 B in, fp16 C out)
    dim3 g1(5, HWN / (128 * NTILES), BATCH);
    gemm_f16<false, true><<<g1, 256, GEMM_SMEM>>>(qkv_w, 0, OC3,
                                                  x, (size_t)CDIM * HWN,
                                                  qkvh, (size_t)OC3 * HWN);

    // K2: depthwise 3x3, 2 rows x 8 px per thread, shfl halos
    dwconv_all<<<(BATCH * OC3 * HWN / 16) / 256, 256>>>(qkvh, dw_w, chd);

    // K3: tensor-core gram, 2-stage cp.async
    dim3 g3(32, BATCH * NHEADS);
    gram_tc<<<g3, 192, GRAM_SMEM>>>(chd, HWN / 32);

    // K4: softmax + fold proj (+ re-zero gram accumulators)
    attn_proj_kernel<<<BATCH, 256>>>(proj_w, temp);

    // K5: out = M_b @ v  (fp16 MMA, fp16 B in, fp32 C out)
    dim3 g5(2, HWN / (128 * NTILES), BATCH);
    gemm_f16<true, false><<<g5, 256, GEMM_SMEM>>>(Mp, (size_t)CDIM * CDIM, CDIM,
                                                  chd + (size_t)2 * CDIM * HWN, (size_t)OC3 * HWN,
                                                  out, (size_t)CDIM * HWN);
}

// round 15
// speedup vs baseline: 1.2782x; 1.0966x over previous
#include <cuda_runtime.h>
#include <cuda_fp16.h>
#include <stdint.h>
#include <math.h>

#define BATCH  4
#define CDIM   192
#define NHEADS 8
#define HDIM   24
#define HWN    65536
#define OC3    576
#define KDIM   192
#define NTILES 8
#define KPADH  200   // A row pad (halves)
#define NPADH  136   // B row pad (halves)

// ---- scratch (device globals; zero-initialized at module load) ----
__device__ __half g_qkvh[(size_t)BATCH * OC3 * HWN];  // 1x1-conv out, fp16
__device__ __half g_ch  [(size_t)BATCH * OC3 * HWN];  // dwconv out, fp16
__device__ float  g_g48 [BATCH * NHEADS * 48 * 48];   // [q;k] full gram (re-zeroed by attn_proj)
__device__ float  g_M   [BATCH * CDIM * CDIM];

__device__ __forceinline__ uint32_t smem_u32(const void* p) {
    uint32_t a;
    asm("{ .reg .u64 t; cvta.to.shared.u64 t, %1; cvt.u32.u64 %0, t; }" : "=r"(a) : "l"(p));
    return a;
}
__device__ __forceinline__ uint32_t h2u(__half2 h) { return *(uint32_t*)&h; }

#define LDSM_X4(r, addr) \
    asm volatile("ldmatrix.sync.aligned.m8n8.x4.shared.b16 {%0,%1,%2,%3}, [%4];" \
        : "=r"((r)[0]), "=r"((r)[1]), "=r"((r)[2]), "=r"((r)[3]) : "r"(addr))
#define LDSM_X4_T(r, addr) \
    asm volatile("ldmatrix.sync.aligned.m8n8.x4.trans.shared.b16 {%0,%1,%2,%3}, [%4];" \
        : "=r"((r)[0]), "=r"((r)[1]), "=r"((r)[2]), "=r"((r)[3]) : "r"(addr))
#define MMA_F16(cc, aa, b0, b1) \
    asm volatile("mma.sync.aligned.m16n8k16.row.col.f32.f16.f16.f32 " \
        "{%0,%1,%2,%3}, {%4,%5,%6,%7}, {%8,%9}, {%0,%1,%2,%3};" \
        : "+f"((cc)[0]), "+f"((cc)[1]), "+f"((cc)[2]), "+f"((cc)[3]) \
        : "r"((aa)[0]), "r"((aa)[1]), "r"((aa)[2]), "r"((aa)[3]), "r"(b0), "r"(b1))
#define CP_ASYNC16(dst, src) \
    asm volatile("cp.async.cg.shared.global [%0], [%1], 16;" :: "r"(dst), "l"(src) : "memory")
#define CP_COMMIT() asm volatile("cp.async.commit_group;" ::: "memory")
#define CP_WAIT(n)  asm volatile("cp.async.wait_group %0;" :: "n"(n) : "memory")

// ============================================================
// fp16 HMMA GEMM: C[b][m][n] = sum_k A[b][m][k] * B[b][k][n]
// (unchanged, validated)
// ============================================================
template<bool BH, bool OH>
__global__ __launch_bounds__(256) void gemm_f16(
    const float* __restrict__ A, size_t aStride, int Mreal,
    const void* __restrict__ Bv, size_t bStride,
    void* __restrict__ C, size_t cStride)
{
    extern __shared__ __half hsm[];
    __half* As  = hsm;                       // [128][KPADH]
    __half* Bs0 = As + 128 * KPADH;          // [64][NPADH]
    __half* Bs1 = Bs0 + 64 * NPADH;

    const float*  Bf = (const float*)Bv;
    const __half* Bh = (const __half*)Bv;
    float*  Cf = (float*)C;
    __half* Ch = (__half*)C;

    int tid  = threadIdx.x;
    int warp = tid >> 5, lane = tid & 31;
    int g = lane >> 2, t = lane & 3;
    int wm0 = (warp >> 1) * 32;
    int wn0 = (warp & 1) * 64;

    int m0    = blockIdx.x * 128;
    int b     = blockIdx.z;
    int nBase = blockIdx.y * (128 * NTILES);
    const float* Ab = A + (size_t)b * aStride;
    size_t bOff = (size_t)b * bStride;
    size_t cOff = (size_t)b * cStride;

    for (int it = tid; it < 128 * 48; it += 256) {
        int row = it / 48, c4 = (it - row * 48) * 4;
        float4 v = make_float4(0.f, 0.f, 0.f, 0.f);
        if (m0 + row < Mreal) v = *(const float4*)&Ab[(size_t)(m0 + row) * KDIM + c4];
        uint2 u;
        u.x = h2u(__float22half2_rn(make_float2(v.x, v.y)));
        u.y = h2u(__float22half2_rn(make_float2(v.z, v.w)));
        *(uint2*)(As + row * KPADH + c4) = u;
    }

    int kr  = tid >> 5;
    int lc4 = lane * 4;
    float4 pf[8];
    uint2  pf2[8];

    float c[2][8][4];
#pragma unroll
    for (int mt = 0; mt < 2; mt++)
#pragma unroll
        for (int nt = 0; nt < 8; nt++)
#pragma unroll
            for (int j = 0; j < 4; j++) c[mt][nt][j] = 0.f;

    const int TOT = NTILES * 3;
    uint32_t sA  = smem_u32(As);
    uint32_t sB0 = smem_u32(Bs0);
    uint32_t sB1 = smem_u32(Bs1);

    {
        if (BH) {
#pragma unroll
            for (int j = 0; j < 8; j++)
                pf2[j] = *(const uint2*)&Bh[bOff + (size_t)(kr + 8 * j) * HWN + nBase + lc4];
        } else {
#pragma unroll
            for (int j = 0; j < 8; j++)
                pf[j] = *(const float4*)&Bf[bOff + (size_t)(kr + 8 * j) * HWN + nBase + lc4];
        }
#pragma unroll
        for (int j = 0; j < 8; j++) {
            uint2 u;
            if (BH) u = pf2[j];
            else {
                u.x = h2u(__float22half2_rn(make_float2(pf[j].x, pf[j].y)));
                u.y = h2u(__float22half2_rn(make_float2(pf[j].z, pf[j].w)));
            }
            *(uint2*)(Bs0 + (kr + 8 * j) * NPADH + lc4) = u;
        }
    }
    __syncthreads();

    for (int i = 0; i < TOT; i++) {
        int tile = i / 3;
        int kc   = i - tile * 3;

        if (i + 1 < TOT) {
            int ntile = (i + 1) / 3;
            int nkc   = (i + 1) - ntile * 3;
            size_t src = bOff + (size_t)(nkc * 64 + kr) * HWN + nBase + ntile * 128 + lc4;
            if (BH) {
#pragma unroll
                for (int j = 0; j < 8; j++) pf2[j] = *(const uint2*)&Bh[src + (size_t)j * 8 * HWN];
            } else {
#pragma unroll
                for (int j = 0; j < 8; j++) pf[j] = *(const float4*)&Bf[src + (size_t)j * 8 * HWN];
            }
        }

        uint32_t sB = (i & 1) ? sB1 : sB0;
#pragma unroll
        for (int ks = 0; ks < 4; ks++) {
            uint32_t a[2][4];
            int kA = kc * 64 + ks * 16 + ((lane >> 4) << 3);
#pragma unroll
            for (int mt = 0; mt < 2; mt++) {
                int row = wm0 + mt * 16 + (lane & 15);
                LDSM_X4(a[mt], sA + (uint32_t)(row * KPADH + kA) * 2);
            }
#pragma unroll
            for (int pr = 0; pr < 4; pr++) {
                uint32_t bq[4];
                int brow = ks * 16 + (lane & 15);
                int bcol = wn0 + pr * 16 + ((lane >> 4) << 3);
                LDSM_X4_T(bq, sB + (uint32_t)(brow * NPADH + bcol) * 2);
                MMA_F16(c[0][2 * pr],     a[0], bq[0], bq[1]);
                MMA_F16(c[1][2 * pr],     a[1], bq[0], bq[1]);
                MMA_F16(c[0][2 * pr + 1], a[0], bq[2], bq[3]);
                MMA_F16(c[1][2 * pr + 1], a[1], bq[2], bq[3]);
            }
        }

        if (kc == 2) {
            int n0 = nBase + tile * 128;
#pragma unroll
            for (int mt = 0; mt < 2; mt++) {
                int row0 = m0 + wm0 + mt * 16 + g;
#pragma unroll
                for (int nt = 0; nt < 8; nt++) {
                    int col = n0 + wn0 + nt * 8 + 2 * t;
                    if (row0 < Mreal) {
                        if (OH) *(__half2*)&Ch[cOff + (size_t)row0 * HWN + col] =
                            __floats2half2_rn(c[mt][nt][0], c[mt][nt][1]);
                        else {
                            float2 v = {c[mt][nt][0], c[mt][nt][1]};
                            *(float2*)&Cf[cOff + (size_t)row0 * HWN + col] = v;
                        }
                    }
                    if (row0 + 8 < Mreal) {
                        if (OH) *(__half2*)&Ch[cOff + (size_t)(row0 + 8) * HWN + col] =
                            __floats2half2_rn(c[mt][nt][2], c[mt][nt][3]);
                        else {
                            float2 v = {c[mt][nt][2], c[mt][nt][3]};
                            *(float2*)&Cf[cOff + (size_t)(row0 + 8) * HWN + col] = v;
                        }
                    }
                    c[mt][nt][0] = 0.f; c[mt][nt][1] = 0.f;
                    c[mt][nt][2] = 0.f; c[mt][nt][3] = 0.f;
                }
            }
        }

        if (i + 1 < TOT) {
            __half* nbuf = (i & 1) ? Bs0 : Bs1;
#pragma unroll
            for (int j = 0; j < 8; j++) {
                uint2 u;
                if (BH) u = pf2[j];
                else {
                    u.x = h2u(__float22half2_rn(make_float2(pf[j].x, pf[j].y)));
                    u.y = h2u(__float22half2_rn(make_float2(pf[j].z, pf[j].w)));
                }
                *(uint2*)(nbuf + (kr + 8 * j) * NPADH + lc4) = u;
            }
            __syncthreads();
        }
    }
}

// ============================================================
// depthwise 3x3: 2 output rows x 8 px per thread, vertical reuse.
// ============================================================
__global__ __launch_bounds__(256) void dwconv_all(
    const __half* __restrict__ in, const float* __restrict__ wAll,
    __half* __restrict__ out)
{
    int idx = blockIdx.x * 256 + threadIdx.x;   // over BATCH*OC3*HWN/16
    int p16 = idx & 4095;
    int bc  = idx >> 12;
    int ch  = bc % OC3;
    int y   = (p16 >> 5) * 2;                   // even row 0..254
    int lane = threadIdx.x & 31;                // == p16 & 31
    int x0 = lane << 3;
    const __half* base = in + (size_t)bc * HWN;

    float w[9];
#pragma unroll
    for (int i = 0; i < 9; i++) w[i] = __ldg(&wAll[ch * 9 + i]);

    uint4 rowv[4];
    bool ok[4];
#pragma unroll
    for (int r = 0; r < 4; r++) {
        int yy = y + r - 1;
        ok[r] = ((unsigned)yy < 256u);
        if (ok[r]) rowv[r] = *(const uint4*)&base[yy * 256 + x0];
    }

    float f[4][10];
#pragma unroll
    for (int r = 0; r < 4; r++) {
        const __half* hp = (const __half*)&rowv[r];
#pragma unroll
        for (int j = 0; j < 8; j++) f[r][j + 1] = __half2float(hp[j]);
        float l = __shfl_up_sync(0xffffffffu, f[r][8], 1);
        float rr = __shfl_down_sync(0xffffffffu, f[r][1], 1);
        f[r][0] = (lane == 0)  ? 0.f : l;
        f[r][9] = (lane == 31) ? 0.f : rr;
    }

    float s0[8], s1[8];
#pragma unroll
    for (int o = 0; o < 8; o++) { s0[o] = 0.f; s1[o] = 0.f; }

#pragma unroll
    for (int kr = 0; kr < 3; kr++) {
        float w0 = w[kr * 3], w1 = w[kr * 3 + 1], w2 = w[kr * 3 + 2];
        if (ok[kr]) {
#pragma unroll
            for (int o = 0; o < 8; o++)
                s0[o] += f[kr][o] * w0 + f[kr][o + 1] * w1 + f[kr][o + 2] * w2;
        }
        if (ok[kr + 1]) {
#pragma unroll
            for (int o = 0; o < 8; o++)
                s1[o] += f[kr + 1][o] * w0 + f[kr + 1][o + 1] * w1 + f[kr + 1][o + 2] * w2;
        }
    }

    __half* obase = out + (size_t)bc * HWN;
    uint4 u0, u1;
    u0.x = h2u(__floats2half2_rn(s0[0], s0[1]));
    u0.y = h2u(__floats2half2_rn(s0[2], s0[3]));
    u0.z = h2u(__floats2half2_rn(s0[4], s0[5]));
    u0.w = h2u(__floats2half2_rn(s0[6], s0[7]));
    u1.x = h2u(__floats2half2_rn(s1[0], s1[1]));
    u1.y = h2u(__floats2half2_rn(s1[2], s1[3]));
    u1.z = h2u(__floats2half2_rn(s1[4], s1[5]));
    u1.w = h2u(__floats2half2_rn(s1[6], s1[7]));
    *(uint4*)&obase[y * 256 + x0]       = u0;
    *(uint4*)&obase[(y + 1) * 256 + x0] = u1;
}

// ============================================================
// Tensor-core gram (validated 2-stage cp.async, 256-px tiles).
// ============================================================
#define GTPAD 264     // 528 B rows: conflict-free ldmatrix
__global__ __launch_bounds__(192) void gram_tc(const __half* __restrict__ chd, int pxPer)
{
    extern __shared__ __half gsm[];          // [2][48][GTPAD]
    __half* buf0 = gsm;
    __half* buf1 = gsm + 48 * GTPAD;

    int bh = blockIdx.y;
    int b = bh >> 3, hh = bh & 7;
    int tid = threadIdx.x;
    int warp = tid >> 5, lane = tid & 31;
    int half = warp / 3;
    int mt   = warp - half * 3;
    int m0 = mt * 16;
    int colBase = half * 128;

    int lrow = tid >> 2;                 // 0..47
    int lseg0 = (tid & 3) * 8;           // 8 consecutive uint4 segs
    int lgch = (lrow < 24) ? (hh * HDIM + lrow) : (CDIM + hh * HDIM + (lrow - 24));
    const __half* lsrc = chd + ((size_t)b * OC3 + lgch) * HWN;

    float c[6][4];
#pragma unroll
    for (int nt = 0; nt < 6; nt++)
#pragma unroll
        for (int j = 0; j < 4; j++) c[nt][j] = 0.f;

    int aRow = m0 + (lane & 15);
    int aK   = colBase + ((lane >> 4) << 3);
    int bRowLoc = ((lane >> 4) << 3) + (lane & 7);
    int bK      = colBase + (((lane >> 3) & 1) << 3);
    uint32_t sb0 = smem_u32(buf0);
    uint32_t sb1 = smem_u32(buf1);
    uint32_t dRow0 = sb0 + (uint32_t)(lrow * GTPAD) * 2;
    uint32_t dRow1 = sb1 + (uint32_t)(lrow * GTPAD) * 2;

    int nStart = blockIdx.x * pxPer;
    int nIters = pxPer / 256;

    {   // prologue: tile 0
        const __half* src = lsrc + nStart;
#pragma unroll
        for (int j = 0; j < 8; j++)
            CP_ASYNC16(dRow0 + (uint32_t)((lseg0 + j) * 8) * 2, src + (lseg0 + j) * 8);
        CP_COMMIT();
    }

    for (int it = 0; it < nIters; it++) {
        if (it + 1 < nIters) {
            const __half* src = lsrc + nStart + (it + 1) * 256;
            uint32_t d = ((it + 1) & 1) ? dRow1 : dRow0;
#pragma unroll
            for (int j = 0; j < 8; j++)
                CP_ASYNC16(d + (uint32_t)((lseg0 + j) * 8) * 2, src + (lseg0 + j) * 8);
            CP_COMMIT();
            CP_WAIT(1);
        } else {
            CP_WAIT(0);
        }
        __syncthreads();

        uint32_t sB = (it & 1) ? sb1 : sb0;
        uint32_t aAddr = sB + (uint32_t)(aRow * GTPAD + aK) * 2;
#pragma unroll
        for (int ks = 0; ks < 8; ks++) {
            uint32_t a[4];
            LDSM_X4(a, aAddr + (uint32_t)(ks * 16) * 2);
#pragma unroll
            for (int nb = 0; nb < 3; nb++) {
                uint32_t bq[4];
                int nr = nb * 16 + bRowLoc;
                LDSM_X4(bq, sB + (uint32_t)(nr * GTPAD + bK + ks * 16) * 2);
                MMA_F16(c[2 * nb],     a, bq[0], bq[1]);
                MMA_F16(c[2 * nb + 1], a, bq[2], bq[3]);
            }
        }
        __syncthreads();
    }

    float* gb = &g_g48[bh * 2304];
    int gm = lane >> 2, gt2 = (lane & 3) * 2;
#pragma unroll
    for (int nt = 0; nt < 6; nt++) {
        int col = nt * 8 + gt2;
        atomicAdd(&gb[(m0 + gm) * 48 + col],     c[nt][0]);
        atomicAdd(&gb[(m0 + gm) * 48 + col + 1], c[nt][1]);
        atomicAdd(&gb[(m0 + gm + 8) * 48 + col],     c[nt][2]);
        atomicAdd(&gb[(m0 + gm + 8) * 48 + col + 1], c[nt][3]);
    }
}

// ============================================================
// softmax + fold proj, parallelized over (b,h) blocks.
// Block bh: softmax attn (24x24) -> M[b][o][h*24+e] for all o,e.
// Then re-zero this head's gram region for the next replay.
// ============================================================
__global__ __launch_bounds__(256) void attn_proj_kernel(
    const float* __restrict__ projw, const float* __restrict__ temp)
{
    __shared__ float attn_s[HDIM * HDIM];
    int bh = blockIdx.x;
    int b = bh >> 3, hh = bh & 7;
    int t = threadIdx.x;
    float* G = &g_g48[bh * 2304];

    if (t < HDIM) {
        int d = t;
        float nq = fmaxf(sqrtf(G[d * 48 + d]), 1e-12f);
        float tm = temp[hh];
        float row[HDIM];
        float mx = -1e30f;
#pragma unroll
        for (int e = 0; e < HDIM; e++) {
            float nk = fmaxf(sqrtf(G[(24 + e) * 48 + 24 + e]), 1e-12f);
            float a = G[d * 48 + 24 + e] / (nq * nk) * tm;
            row[e] = a; mx = fmaxf(mx, a);
        }
        float s = 0.f;
#pragma unroll
        for (int e = 0; e < HDIM; e++) { row[e] = expf(row[e] - mx); s += row[e]; }
        float inv = 1.f / s;
#pragma unroll
        for (int e = 0; e < HDIM; e++) attn_s[d * 24 + e] = row[e] * inv;
    }
    __syncthreads();     // attn ready; all G reads done

    // M[b][o][hh*24+e] = sum_d proj[o][hh*24+d] * attn[d][e]
    // 192*24 = 4608 entries, 18 per thread
#pragma unroll
    for (int i = 0; i < 18; i++) {
        int idx = i * 256 + t;
        int o = idx / 24, e = idx - o * 24;
        const float* pr = &projw[o * CDIM + hh * HDIM];
        float acc = 0.f;
#pragma unroll
        for (int d = 0; d < HDIM; d++)
            acc += __ldg(&pr[d]) * attn_s[d * 24 + e];
        g_M[((size_t)b * CDIM + o) * CDIM + hh * HDIM + e] = acc;
    }

    // re-zero this head's gram region for the next graph replay
    for (int i = t; i < 2304; i += 256) G[i] = 0.f;
}

// ============================================================
extern "C" void kernel_launch(void* const* d_in, const int* in_sizes, int n_in,
                              void* d_out, int out_size)
{
    const float* x      = (const float*)d_in[0];
    const float* qkv_w  = (const float*)d_in[1];
    const float* dw_w   = (const float*)d_in[2];
    const float* proj_w = (const float*)d_in[3];
    const float* temp   = (const float*)d_in[4];
    float* out = (float*)d_out;

    __half *qkvh, *chd;
    float *Mp;
    cudaGetSymbolAddress((void**)&qkvh, g_qkvh);
    cudaGetSymbolAddress((void**)&chd,  g_ch);
    cudaGetSymbolAddress((void**)&Mp,   g_M);

    const int GEMM_SMEM = (128 * KPADH + 2 * 64 * NPADH) * 2;
    const int GRAM_SMEM = 2 * 48 * GTPAD * 2;
    cudaFuncSetAttribute(gemm_f16<false, true>, cudaFuncAttributeMaxDynamicSharedMemorySize, GEMM_SMEM);
    cudaFuncSetAttribute(gemm_f16<true, false>, cudaFuncAttributeMaxDynamicSharedMemorySize, GEMM_SMEM);
    cudaFuncSetAttribute(gram_tc, cudaFuncAttributeMaxDynamicSharedMemorySize, GRAM_SMEM);

    // K1: qkv = W_qkv @ x  (fp16 MMA, fp32 B in, fp16 C out)
    dim3 g1(5, HWN / (128 * NTILES), BATCH);
    gemm_f16<false, true><<<g1, 256, GEMM_SMEM>>>(qkv_w, 0, OC3,
                                                  x, (size_t)CDIM * HWN,
                                                  qkvh, (size_t)OC3 * HWN);

    // K2: depthwise 3x3, 2 rows x 8 px per thread, shfl halos
    dwconv_all<<<(BATCH * OC3 * HWN / 16) / 256, 256>>>(qkvh, dw_w, chd);

    // K3: tensor-core gram, 2-stage cp.async
    dim3 g3(32, BATCH * NHEADS);
    gram_tc<<<g3, 192, GRAM_SMEM>>>(chd, HWN / 32);

    // K4: softmax + fold proj, 32-way parallel (+ re-zero gram)
    attn_proj_kernel<<<BATCH * NHEADS, 256>>>(proj_w, temp);

    // K5: out = M_b @ v  (fp16 MMA, fp16 B in, fp32 C out)
    dim3 g5(2, HWN / (128 * NTILES), BATCH);
    gemm_f16<true, false><<<g5, 256, GEMM_SMEM>>>(Mp, (size_t)CDIM * CDIM, CDIM,
                                                  chd + (size_t)2 * CDIM * HWN, (size_t)OC3 * HWN,
                                                  out, (size_t)CDIM * HWN);
}